// round 6
// baseline (speedup 1.0000x reference)
#include <cuda_runtime.h>

#define RPB 64           // rows per block
#define TPB 128          // 2 threads per row
#define NSTEPS 16

// Scratch section strides (floats). Half-sections offset by +16 words so the
// two halves of a pair land in disjoint bank groups (4112%32==16, 2064%32==16).
#define SSTR 2064        // 32-slot scratch section stride (32*64 + 16)
#define HSTR 4112        // 64-slot scratch section stride (64*64 + 16)

__device__ __forceinline__ float gelu_exact(float v) {
    return 0.5f * v * (1.0f + erff(v * 0.70710678118654752f));
}

// ---- register-array dot products against warp-uniform weights ---------------
__device__ __forceinline__ float dot32(const float* __restrict__ in,
                                       const float* __restrict__ W) {
    const float4* w4 = reinterpret_cast<const float4*>(W);
    float a0 = 0.f, a1 = 0.f, a2 = 0.f, a3 = 0.f;
#pragma unroll
    for (int i = 0; i < 8; i++) {
        float4 w = __ldg(w4 + i);
        a0 = fmaf(w.x, in[4 * i + 0], a0);
        a1 = fmaf(w.y, in[4 * i + 1], a1);
        a2 = fmaf(w.z, in[4 * i + 2], a2);
        a3 = fmaf(w.w, in[4 * i + 3], a3);
    }
    return (a0 + a1) + (a2 + a3);
}

__device__ __forceinline__ float dot64r(const float* __restrict__ in,
                                        const float* __restrict__ W) {
    const float4* w4 = reinterpret_cast<const float4*>(W);
    float a0 = 0.f, a1 = 0.f, a2 = 0.f, a3 = 0.f;
#pragma unroll
    for (int i = 0; i < 16; i++) {
        float4 w = __ldg(w4 + i);
        a0 = fmaf(w.x, in[4 * i + 0], a0);
        a1 = fmaf(w.y, in[4 * i + 1], a1);
        a2 = fmaf(w.z, in[4 * i + 2], a2);
        a3 = fmaf(w.w, in[4 * i + 3], a3);
    }
    return (a0 + a1) + (a2 + a3);
}

__device__ __forceinline__ float dot100(const float* __restrict__ in,
                                        const float* __restrict__ W) {
    const float4* w4 = reinterpret_cast<const float4*>(W);
    float a0 = 0.f, a1 = 0.f, a2 = 0.f, a3 = 0.f;
#pragma unroll
    for (int i = 0; i < 25; i++) {
        float4 w = __ldg(w4 + i);
        a0 = fmaf(w.x, in[4 * i + 0], a0);
        a1 = fmaf(w.y, in[4 * i + 1], a1);
        a2 = fmaf(w.z, in[4 * i + 2], a2);
        a3 = fmaf(w.w, in[4 * i + 3], a3);
    }
    return (a0 + a1) + (a2 + a3);
}

// Two dots sharing one weight stream (ky/kz and vy/vz reuse)
__device__ __forceinline__ void dot32x2(const float* __restrict__ a,
                                        const float* __restrict__ b,
                                        const float* __restrict__ W,
                                        float& ra, float& rb) {
    const float4* w4 = reinterpret_cast<const float4*>(W);
    float x0 = 0.f, x1 = 0.f, x2 = 0.f, x3 = 0.f;
    float y0 = 0.f, y1 = 0.f, y2 = 0.f, y3 = 0.f;
#pragma unroll
    for (int i = 0; i < 8; i++) {
        float4 w = __ldg(w4 + i);
        x0 = fmaf(w.x, a[4 * i + 0], x0);  y0 = fmaf(w.x, b[4 * i + 0], y0);
        x1 = fmaf(w.y, a[4 * i + 1], x1);  y1 = fmaf(w.y, b[4 * i + 1], y1);
        x2 = fmaf(w.z, a[4 * i + 2], x2);  y2 = fmaf(w.z, b[4 * i + 2], y2);
        x3 = fmaf(w.w, a[4 * i + 3], x3);  y3 = fmaf(w.w, b[4 * i + 3], y3);
    }
    ra = (x0 + x1) + (x2 + x3);
    rb = (y0 + y1) + (y2 + y3);
}

// ---- 64x64 GEMV, pair-split: each thread produces its own 32 outputs --------
// out[jo] = dot(in_full, W[jo]) + b[jo]; in is this thread's half, partner's
// partial arrives via one shfl.bfly per output. Outputs go to scratch S.
__device__ __forceinline__ void gemv64(const float* __restrict__ in,
                                       const float* __restrict__ W,
                                       const float* __restrict__ b,
                                       float* __restrict__ S, int sstr,
                                       int h, int p) {
    const int co = h * 32;
#pragma unroll 2
    for (int jj = 0; jj < 32; jj++) {
        int jo = co + jj;            // my output row
        int jt = 32 - co + jj;       // partner's output row (I supply partial)
        float po = dot32(in, W + jo * 64 + co);
        float pt = dot32(in, W + jt * 64 + co);
        float r = __shfl_xor_sync(0xFFFFFFFFu, pt, 1);
        S[h * sstr + (jj << 6) + p] = po + r + __ldg(b + jo);
    }
}

// Dual-input variant (shared weight stream), two output scratch regions
__device__ __forceinline__ void gemv64_2(const float* __restrict__ inA,
                                         const float* __restrict__ inB,
                                         const float* __restrict__ W,
                                         const float* __restrict__ b,
                                         float* __restrict__ SA, int sa,
                                         float* __restrict__ SB, int sb,
                                         int h, int p) {
    const int co = h * 32;
#pragma unroll 2
    for (int jj = 0; jj < 32; jj++) {
        int jo = co + jj, jt = 32 - co + jj;
        float poA, poB, ptA, ptB;
        dot32x2(inA, inB, W + jo * 64 + co, poA, poB);
        dot32x2(inA, inB, W + jt * 64 + co, ptA, ptB);
        float rA = __shfl_xor_sync(0xFFFFFFFFu, ptA, 1);
        float rB = __shfl_xor_sync(0xFFFFFFFFu, ptB, 1);
        float bb = __ldg(b + jo);
        SA[h * sa + (jj << 6) + p] = poA + rA + bb;
        SB[h * sb + (jj << 6) + p] = poB + rB + bb;
    }
}

__device__ __forceinline__ void rd32(float* __restrict__ r,
                                     const float* __restrict__ S, int sstr,
                                     int h, int p) {
#pragma unroll
    for (int l = 0; l < 32; l++) r[l] = S[h * sstr + (l << 6) + p];
}

// LayerNorm over the 64-vector held as reg halves across the pair
__device__ __forceinline__ void ln_pair(float* __restrict__ v,
                                        const float* __restrict__ g,
                                        const float* __restrict__ b, int h) {
    float s = 0.f;
#pragma unroll
    for (int l = 0; l < 32; l++) s += v[l];
    s += __shfl_xor_sync(0xFFFFFFFFu, s, 1);
    float m = s * (1.0f / 64.0f);
    float q = 0.f;
#pragma unroll
    for (int l = 0; l < 32; l++) { float d = v[l] - m; q = fmaf(d, d, q); }
    q += __shfl_xor_sync(0xFFFFFFFFu, q, 1);
    float inv = rsqrtf(q * (1.0f / 64.0f) + 1e-5f);
#pragma unroll
    for (int l = 0; l < 32; l++)
        v[l] = fmaf((v[l] - m) * inv, __ldg(g + h * 32 + l), __ldg(b + h * 32 + l));
}

// v := LN(v + FFN(v)); hidden=128 (64 owned per thread), hid via sH, out via sV
__device__ __forceinline__ void ffn(float* __restrict__ v,
        const float* __restrict__ w1, const float* __restrict__ b1,
        const float* __restrict__ w2, const float* __restrict__ b2,
        const float* __restrict__ g,  const float* __restrict__ bb,
        float* __restrict__ sH, float* __restrict__ sV, int h, int p) {
    const int co = h * 32;
#pragma unroll 2
    for (int jj = 0; jj < 64; jj++) {
        int jo = h * 64 + jj, jt = 64 - h * 64 + jj;
        float po = dot32(v, w1 + jo * 64 + co);
        float pt = dot32(v, w1 + jt * 64 + co);
        float r = __shfl_xor_sync(0xFFFFFFFFu, pt, 1);
        sH[h * HSTR + (jj << 6) + p] = gelu_exact(po + r + __ldg(b1 + jo));
    }
    float hid[64];
#pragma unroll
    for (int l = 0; l < 64; l++) hid[l] = sH[h * HSTR + (l << 6) + p];
    const int ho = h * 64;
#pragma unroll 2
    for (int jj = 0; jj < 32; jj++) {
        int jo = co + jj, jt = 32 - co + jj;
        float po = dot64r(hid, w2 + jo * 128 + ho);
        float pt = dot64r(hid, w2 + jt * 128 + ho);
        float r = __shfl_xor_sync(0xFFFFFFFFu, pt, 1);
        sV[h * SSTR + (jj << 6) + p] = po + r + __ldg(b2 + jo);
    }
#pragma unroll
    for (int l = 0; l < 32; l++) v[l] += sV[h * SSTR + (l << 6) + p];
    ln_pair(v, g, bb, h);
}

__global__ void __launch_bounds__(TPB, 2)
trm_kernel(const float* __restrict__ x,
           const float* __restrict__ W_in,     const float* __restrict__ b_in,
           const float* __restrict__ g_in,     const float* __restrict__ be_in,
           const float* __restrict__ z_in_w,   const float* __restrict__ z_in_b,
           const float* __restrict__ z_out_w,  const float* __restrict__ z_out_b,
           const float* __restrict__ z_ffn_w1, const float* __restrict__ z_ffn_b1,
           const float* __restrict__ z_ffn_w2, const float* __restrict__ z_ffn_b2,
           const float* __restrict__ zn1_g,    const float* __restrict__ zn1_b,
           const float* __restrict__ zn2_g,    const float* __restrict__ zn2_b,
           const float* __restrict__ y_in_w,   const float* __restrict__ y_in_b,
           const float* __restrict__ y_out_w,  const float* __restrict__ y_out_b,
           const float* __restrict__ y_ffn_w1, const float* __restrict__ y_ffn_b1,
           const float* __restrict__ y_ffn_w2, const float* __restrict__ y_ffn_b2,
           const float* __restrict__ yn1_g,    const float* __restrict__ yn1_b,
           const float* __restrict__ yn2_g,    const float* __restrict__ yn2_b,
           const float* __restrict__ W_out,    const float* __restrict__ b_out,
           float* __restrict__ out, int Btotal) {
    extern __shared__ float sh[];
    float* skx = sh;                    // 4112 floats
    float* svx = sh + 4112;             // 4112
    float* sV  = sh + 8224;             // 4112
    float* sH  = sh + 12336;            // 8224   -> total 20560 floats = 82240 B

    const int tid = threadIdx.x;
    const int p = tid >> 1;             // row within block
    const int h = tid & 1;              // half (owns elems [32h, 32h+32))
    const int row  = blockIdx.x * RPB + p;
    const int rowc = (row < Btotal) ? row : (Btotal - 1);

    // ---- input projection: x_proj = gelu(LN(x @ W_in^T + b_in)) ----
    float v[32];
    {
        float xv[100];
        const float4* x4 = reinterpret_cast<const float4*>(x + (size_t)rowc * 200 + 100 * h);
#pragma unroll
        for (int i = 0; i < 25; i++) {
            float4 w = __ldg(x4 + i);
            xv[4 * i + 0] = w.x; xv[4 * i + 1] = w.y;
            xv[4 * i + 2] = w.z; xv[4 * i + 3] = w.w;
        }
        const int co = h * 100;
#pragma unroll 1
        for (int jj = 0; jj < 32; jj++) {
            int jo = h * 32 + jj, jt = 32 - h * 32 + jj;
            float po = dot100(xv, W_in + jo * 200 + co);
            float pt = dot100(xv, W_in + jt * 200 + co);
            float r = __shfl_xor_sync(0xFFFFFFFFu, pt, 1);
            sV[h * SSTR + (jj << 6) + p] = po + r + __ldg(b_in + jo);
        }
        rd32(v, sV, SSTR, h, p);
        ln_pair(v, g_in, be_in, h);
#pragma unroll
        for (int l = 0; l < 32; l++) v[l] = gelu_exact(v[l]);
    }

    // ---- loop-invariant k_x, v_x -> persistent scratch ----
    gemv64(v, z_in_w + 4096, z_in_b + 64,  skx, SSTR, h, p);
    gemv64(v, z_in_w + 8192, z_in_b + 128, svx, SSTR, h, p);

    float yv[32], zv[32];
#pragma unroll
    for (int l = 0; l < 32; l++) { yv[l] = 0.f; zv[l] = 0.f; }

    // ---- 16 recursion steps ----
#pragma unroll 1
    for (int s = 0; s < NSTEPS; s++) {
        // q of token z (the only q ever consumed)
        float q[32];
        gemv64(zv, z_in_w, z_in_b, sV, SSTR, h, p);
        rd32(q, sV, SSTR, h, p);

        // k_y -> sV, k_z -> sH (shared weight stream); logits per owned head
        gemv64_2(yv, zv, z_in_w + 4096, z_in_b + 64, sV, SSTR, sH, HSTR, h, p);
        float s0[2] = {0.f, 0.f}, s1[2] = {0.f, 0.f}, s2[2] = {0.f, 0.f};
#pragma unroll
        for (int l = 0; l < 32; l++) {
            int hh = l >> 4;
            float kxl = skx[h * SSTR + (l << 6) + p];
            float kyl = sV [h * SSTR + (l << 6) + p];
            float kzl = sH [h * HSTR + (l << 6) + p];
            s0[hh] = fmaf(q[l], kxl, s0[hh]);
            s1[hh] = fmaf(q[l], kyl, s1[hh]);
            s2[hh] = fmaf(q[l], kzl, s2[hh]);
        }
        float w0[2], w1a[2], w2a[2];
#pragma unroll
        for (int hh = 0; hh < 2; hh++) {
            float a0 = s0[hh] * 0.25f, a1 = s1[hh] * 0.25f, a2 = s2[hh] * 0.25f;
            float mx = fmaxf(a0, fmaxf(a1, a2));
            float e0 = expf(a0 - mx), e1 = expf(a1 - mx), e2 = expf(a2 - mx);
            float rs = 1.0f / (e0 + e1 + e2);
            w0[hh] = e0 * rs; w1a[hh] = e1 * rs; w2a[hh] = e2 * rs;
        }

        // v_y -> sV, v_z -> sH; blend with v_x into attention output o
        gemv64_2(yv, zv, z_in_w + 8192, z_in_b + 128, sV, SSTR, sH, HSTR, h, p);
        float o[32];
#pragma unroll
        for (int l = 0; l < 32; l++) {
            int hh = l >> 4;
            o[l] = w0[hh]  * svx[h * SSTR + (l << 6) + p]
                 + w1a[hh] * sV [h * SSTR + (l << 6) + p]
                 + w2a[hh] * sH [h * HSTR + (l << 6) + p];
        }

        // z_res = LN(z + o @ z_out_w^T + z_out_b)
        gemv64(o, z_out_w, z_out_b, sV, SSTR, h, p);
#pragma unroll
        for (int l = 0; l < 32; l++) zv[l] += sV[h * SSTR + (l << 6) + p];
        ln_pair(zv, zn1_g, zn1_b, h);

        // z2 = LN(z_res + FFN_z(z_res))
        ffn(zv, z_ffn_w1, z_ffn_b1, z_ffn_w2, z_ffn_b2, zn2_g, zn2_b, sH, sV, h, p);

        // cross-attn: ca = (z2 @ Wv_y^T + bv_y) @ y_out_w^T + y_out_b
        float t[32];
        gemv64(zv, y_in_w + 8192, y_in_b + 128, sV, SSTR, h, p);
        rd32(t, sV, SSTR, h, p);
        gemv64(t, y_out_w, y_out_b, sV, SSTR, h, p);
#pragma unroll
        for (int l = 0; l < 32; l++) yv[l] += sV[h * SSTR + (l << 6) + p];
        ln_pair(yv, yn1_g, yn1_b, h);

        // y2 = LN(y_res + FFN_y(y_res))
        ffn(yv, y_ffn_w1, y_ffn_b1, y_ffn_w2, y_ffn_b2, yn2_g, yn2_b, sH, sV, h, p);
    }

    // ---- output: (y @ W_out^T + b_out)[:, 0] ----
    float acc = 0.f;
#pragma unroll
    for (int l = 0; l < 32; l++) acc = fmaf(yv[l], __ldg(W_out + h * 32 + l), acc);
    acc += __shfl_xor_sync(0xFFFFFFFFu, acc, 1);
    if (h == 0 && row < Btotal) out[row] = acc + __ldg(b_out);
}

extern "C" void kernel_launch(void* const* d_in, const int* in_sizes, int n_in,
                              void* d_out, int out_size) {
    const float* x        = (const float*)d_in[0];
    const float* W_in     = (const float*)d_in[1];
    const float* b_in     = (const float*)d_in[2];
    const float* g_in     = (const float*)d_in[3];
    const float* be_in    = (const float*)d_in[4];
    const float* z_in_w   = (const float*)d_in[5];
    const float* z_in_b   = (const float*)d_in[6];
    const float* z_out_w  = (const float*)d_in[7];
    const float* z_out_b  = (const float*)d_in[8];
    const float* z_ffn_w1 = (const float*)d_in[9];
    const float* z_ffn_b1 = (const float*)d_in[10];
    const float* z_ffn_w2 = (const float*)d_in[11];
    const float* z_ffn_b2 = (const float*)d_in[12];
    const float* zn1_g    = (const float*)d_in[13];
    const float* zn1_b    = (const float*)d_in[14];
    const float* zn2_g    = (const float*)d_in[15];
    const float* zn2_b    = (const float*)d_in[16];
    const float* y_in_w   = (const float*)d_in[17];
    const float* y_in_b   = (const float*)d_in[18];
    const float* y_out_w  = (const float*)d_in[19];
    const float* y_out_b  = (const float*)d_in[20];
    const float* y_ffn_w1 = (const float*)d_in[21];
    const float* y_ffn_b1 = (const float*)d_in[22];
    const float* y_ffn_w2 = (const float*)d_in[23];
    const float* y_ffn_b2 = (const float*)d_in[24];
    const float* yn1_g    = (const float*)d_in[25];
    const float* yn1_b    = (const float*)d_in[26];
    const float* yn2_g    = (const float*)d_in[27];
    const float* yn2_b    = (const float*)d_in[28];
    const float* W_out    = (const float*)d_in[29];
    const float* b_out    = (const float*)d_in[30];
    float* out = (float*)d_out;

    int B = in_sizes[0] / 200;
    size_t smem = 20560 * sizeof(float);   // 82240 B
    cudaFuncSetAttribute(trm_kernel, cudaFuncAttributeMaxDynamicSharedMemorySize, (int)smem);

    dim3 grid((B + RPB - 1) / RPB);
    trm_kernel<<<grid, TPB, smem>>>(x, W_in, b_in, g_in, be_in,
                                    z_in_w, z_in_b, z_out_w, z_out_b,
                                    z_ffn_w1, z_ffn_b1, z_ffn_w2, z_ffn_b2,
                                    zn1_g, zn1_b, zn2_g, zn2_b,
                                    y_in_w, y_in_b, y_out_w, y_out_b,
                                    y_ffn_w1, y_ffn_b1, y_ffn_w2, y_ffn_b2,
                                    yn1_g, yn1_b, yn2_g, yn2_b,
                                    W_out, b_out, out, B);
}

// round 7
// speedup vs baseline: 1.3649x; 1.3649x over previous
#include <cuda_runtime.h>

#define TPB    128
#define ROWS   64
#define ST     68     // row stride (floats) for 64-col buffers
#define SH     136    // row stride (floats) for scratch s_h (S0 @0, S1 @68, hidden @0..127)
#define NSTEPS 16

__device__ __forceinline__ float gelu_exact(float v) {
    return 0.5f * v * (1.0f + erff(v * 0.70710678118654752f));
}

// ---------------------------------------------------------------------------
// GEMM: out[r][c] = sum_k in[r][k] * W[c][k] + bias[c]   (r,c in [0,64))
// 128 threads: tx = tid&15 -> cols {4tx..4tx+3}, ty = tid>>4 -> rows {ty+8i}.
// Per-thread 8x4 register tile; in per-lane from smem (distinct banks),
// W per-lane distinct from global. mode: 0=store, 1=gelu+store, 2=add-dest.
// ---------------------------------------------------------------------------
__device__ __forceinline__ void gemm(const float* sIn, int inStr,
                                     const float* __restrict__ W, int K,
                                     const float* __restrict__ bias,
                                     float* sOut, int outStr, int outOff,
                                     int mode, int tx, int ty)
{
    float acc[8][4];
#pragma unroll
    for (int i = 0; i < 8; i++)
#pragma unroll
        for (int j = 0; j < 4; j++) acc[i][j] = 0.f;

    const float* w0 = W + (4 * tx + 0) * K;
    const float* w1 = W + (4 * tx + 1) * K;
    const float* w2 = W + (4 * tx + 2) * K;
    const float* w3 = W + (4 * tx + 3) * K;
    const float* ip = sIn + ty * inStr;
    const int st8 = inStr * 8;

#pragma unroll 2
    for (int k = 0; k < K; k += 4) {
        float4 a0 = __ldg((const float4*)(w0 + k));
        float4 a1 = __ldg((const float4*)(w1 + k));
        float4 a2 = __ldg((const float4*)(w2 + k));
        float4 a3 = __ldg((const float4*)(w3 + k));
#pragma unroll
        for (int i = 0; i < 8; i++) {
            float4 b = *(const float4*)(ip + i * st8 + k);
            acc[i][0] = fmaf(b.x, a0.x, fmaf(b.y, a0.y, fmaf(b.z, a0.z, fmaf(b.w, a0.w, acc[i][0]))));
            acc[i][1] = fmaf(b.x, a1.x, fmaf(b.y, a1.y, fmaf(b.z, a1.z, fmaf(b.w, a1.w, acc[i][1]))));
            acc[i][2] = fmaf(b.x, a2.x, fmaf(b.y, a2.y, fmaf(b.z, a2.z, fmaf(b.w, a2.w, acc[i][2]))));
            acc[i][3] = fmaf(b.x, a3.x, fmaf(b.y, a3.y, fmaf(b.z, a3.z, fmaf(b.w, a3.w, acc[i][3]))));
        }
    }

    float4 bb = __ldg((const float4*)(bias + 4 * tx));
#pragma unroll
    for (int i = 0; i < 8; i++) {
        int r = ty + 8 * i;
        float* op = sOut + r * outStr + outOff + 4 * tx;
        float4 v;
        v.x = acc[i][0] + bb.x; v.y = acc[i][1] + bb.y;
        v.z = acc[i][2] + bb.z; v.w = acc[i][3] + bb.w;
        if (mode == 1) {
            v.x = gelu_exact(v.x); v.y = gelu_exact(v.y);
            v.z = gelu_exact(v.z); v.w = gelu_exact(v.w);
        } else if (mode == 2) {
            float4 d = *(const float4*)op;
            v.x += d.x; v.y += d.y; v.z += d.z; v.w += d.w;
        }
        *(float4*)op = v;
    }
}

// LayerNorm one row (2 threads/row: h owns cols [32h,32h+32)); optional gelu after.
__device__ __forceinline__ void ln_row(float* buf, int str,
                                       const float* __restrict__ g,
                                       const float* __restrict__ b,
                                       bool dogelu, int row, int h)
{
    float* p = buf + row * str + h * 32;
    float4 v[8];
#pragma unroll
    for (int i = 0; i < 8; i++) v[i] = *(const float4*)(p + 4 * i);
    float s = 0.f;
#pragma unroll
    for (int i = 0; i < 8; i++) s += (v[i].x + v[i].y) + (v[i].z + v[i].w);
    s += __shfl_xor_sync(0xFFFFFFFFu, s, 1);
    float m = s * (1.0f / 64.0f);
    float q = 0.f;
#pragma unroll
    for (int i = 0; i < 8; i++) {
        float dx = v[i].x - m, dy = v[i].y - m, dz = v[i].z - m, dw = v[i].w - m;
        q = fmaf(dx, dx, q); q = fmaf(dy, dy, q);
        q = fmaf(dz, dz, q); q = fmaf(dw, dw, q);
    }
    q += __shfl_xor_sync(0xFFFFFFFFu, q, 1);
    float inv = rsqrtf(q * (1.0f / 64.0f) + 1e-5f);
#pragma unroll
    for (int i = 0; i < 8; i++) {
        float4 gg = __ldg((const float4*)(g + h * 32 + 4 * i));
        float4 bb = __ldg((const float4*)(b + h * 32 + 4 * i));
        float4 r;
        r.x = fmaf((v[i].x - m) * inv, gg.x, bb.x);
        r.y = fmaf((v[i].y - m) * inv, gg.y, bb.y);
        r.z = fmaf((v[i].z - m) * inv, gg.z, bb.z);
        r.w = fmaf((v[i].w - m) * inv, gg.w, bb.w);
        if (dogelu) {
            r.x = gelu_exact(r.x); r.y = gelu_exact(r.y);
            r.z = gelu_exact(r.z); r.w = gelu_exact(r.w);
        }
        *(float4*)(p + 4 * i) = r;
    }
}

__global__ void __launch_bounds__(TPB, 2)
trm_kernel(const float* __restrict__ x,
           const float* __restrict__ W_in,     const float* __restrict__ b_in,
           const float* __restrict__ g_in,     const float* __restrict__ be_in,
           const float* __restrict__ z_in_w,   const float* __restrict__ z_in_b,
           const float* __restrict__ z_out_w,  const float* __restrict__ z_out_b,
           const float* __restrict__ z_ffn_w1, const float* __restrict__ z_ffn_b1,
           const float* __restrict__ z_ffn_w2, const float* __restrict__ z_ffn_b2,
           const float* __restrict__ zn1_g,    const float* __restrict__ zn1_b,
           const float* __restrict__ zn2_g,    const float* __restrict__ zn2_b,
           const float* __restrict__ y_in_w,   const float* __restrict__ y_in_b,
           const float* __restrict__ y_out_w,  const float* __restrict__ y_out_b,
           const float* __restrict__ y_ffn_w1, const float* __restrict__ y_ffn_b1,
           const float* __restrict__ y_ffn_w2, const float* __restrict__ y_ffn_b2,
           const float* __restrict__ yn1_g,    const float* __restrict__ yn1_b,
           const float* __restrict__ yn2_g,    const float* __restrict__ yn2_b,
           const float* __restrict__ W_out,    const float* __restrict__ b_out,
           float* __restrict__ out, int Btotal)
{
    extern __shared__ float sm[];
    float* s_kx = sm;                    // 64*68
    float* s_vx = sm + ROWS * ST;        // 64*68
    float* s_y  = sm + 2 * ROWS * ST;    // 64*68
    float* s_z  = sm + 3 * ROWS * ST;    // 64*68
    float* s_h  = sm + 4 * ROWS * ST;    // 64*136 : S0 = cols[0:64), S1 = cols[68:132)

    const int tid = threadIdx.x;
    const int tx = tid & 15, ty = tid >> 4;     // GEMM mapping
    const int row = tid >> 1, h = tid & 1;      // elementwise mapping
    const int row0 = blockIdx.x * ROWS;

    const float* Wq = z_in_w;
    const float* Wk = z_in_w + 64 * 64;
    const float* Wv = z_in_w + 128 * 64;
    const float* bq = z_in_b;
    const float* bk = z_in_b + 64;
    const float* bv = z_in_b + 128;
    const float* Wvy = y_in_w + 128 * 64;
    const float* bvy = y_in_b + 128;

    // ---- prologue: x_proj = gelu(LN(x @ W_in^T + b_in)) -> s_z ----
    gemm(x + (size_t)row0 * 200, 200, W_in, 200, b_in, s_z, ST, 0, 0, tx, ty);
    __syncthreads();
    ln_row(s_z, ST, g_in, be_in, true, row, h);
    __syncthreads();

    // kx = xp @ Wk^T + bk ; vx = xp @ Wv^T + bv
    gemm(s_z, ST, Wk, 64, bk, s_kx, ST, 0, 0, tx, ty);
    gemm(s_z, ST, Wv, 64, bv, s_vx, ST, 0, 0, tx, ty);
    __syncthreads();

    // zero y, z
    {
        float* yp = s_y + row * ST + 32 * h;
        float* zp = s_z + row * ST + 32 * h;
        const float4 zz = make_float4(0.f, 0.f, 0.f, 0.f);
#pragma unroll
        for (int i = 0; i < 8; i++) { *(float4*)(yp + 4 * i) = zz; *(float4*)(zp + 4 * i) = zz; }
    }
    __syncthreads();

    // ---- 16 recursion steps ----
#pragma unroll 1
    for (int s = 0; s < NSTEPS; s++) {
        float rs0[2], rs1[2], rs2[2], rw0[2], rw1[2], rw2[2];

        // q(z) -> S0
        gemm(s_z, ST, Wq, 64, bq, s_h, SH, 0, 0, tx, ty);
        __syncthreads();
        // k(y) -> S1
        gemm(s_y, ST, Wk, 64, bk, s_h, SH, 68, 0, tx, ty);
        __syncthreads();
        // logits vs kx, ky
        {
            const float* qp  = s_h + row * SH;
            const float* kyp = s_h + row * SH + 68;
            const float* kxp = s_kx + row * ST;
#pragma unroll
            for (int hh = 0; hh < 2; hh++) {
                int d0 = (2 * h + hh) * 16;
                float a = 0.f, b2 = 0.f;
#pragma unroll
                for (int d = 0; d < 16; d++) {
                    float qv = qp[d0 + d];
                    a  = fmaf(qv, kxp[d0 + d], a);
                    b2 = fmaf(qv, kyp[d0 + d], b2);
                }
                rs0[hh] = a; rs1[hh] = b2;
            }
        }
        __syncthreads();
        // k(z) -> S1
        gemm(s_z, ST, Wk, 64, bk, s_h, SH, 68, 0, tx, ty);
        __syncthreads();
        // logits vs kz + softmax
        {
            const float* qp  = s_h + row * SH;
            const float* kzp = s_h + row * SH + 68;
#pragma unroll
            for (int hh = 0; hh < 2; hh++) {
                int d0 = (2 * h + hh) * 16;
                float c = 0.f;
#pragma unroll
                for (int d = 0; d < 16; d++) c = fmaf(qp[d0 + d], kzp[d0 + d], c);
                rs2[hh] = c;
                float a0 = rs0[hh] * 0.25f, a1 = rs1[hh] * 0.25f, a2 = c * 0.25f;
                float mx = fmaxf(a0, fmaxf(a1, a2));
                float e0 = expf(a0 - mx), e1 = expf(a1 - mx), e2 = expf(a2 - mx);
                float rs = 1.0f / (e0 + e1 + e2);
                rw0[hh] = e0 * rs; rw1[hh] = e1 * rs; rw2[hh] = e2 * rs;
            }
        }
        __syncthreads();
        // v(y) -> S1
        gemm(s_y, ST, Wv, 64, bv, s_h, SH, 68, 0, tx, ty);
        __syncthreads();
        // blend1: S0 = w0*vx + w1*vy   (q dead)
        {
            float* s0p = s_h + row * SH + 32 * h;
            const float* s1p = s_h + row * SH + 68 + 32 * h;
            const float* vxp = s_vx + row * ST + 32 * h;
#pragma unroll
            for (int j = 0; j < 32; j++) {
                int hh = j >> 4;
                s0p[j] = fmaf(rw0[hh], vxp[j], rw1[hh] * s1p[j]);
            }
        }
        __syncthreads();
        // v(z) -> S1
        gemm(s_z, ST, Wv, 64, bv, s_h, SH, 68, 0, tx, ty);
        __syncthreads();
        // blend2: S0 += w2*vz
        {
            float* s0p = s_h + row * SH + 32 * h;
            const float* s1p = s_h + row * SH + 68 + 32 * h;
#pragma unroll
            for (int j = 0; j < 32; j++) s0p[j] = fmaf(rw2[j >> 4], s1p[j], s0p[j]);
        }
        __syncthreads();
        // z += S0 @ z_out_w^T + z_out_b ; LN(zn1)
        gemm(s_h, SH, z_out_w, 64, z_out_b, s_z, ST, 0, 2, tx, ty);
        __syncthreads();
        ln_row(s_z, ST, zn1_g, zn1_b, false, row, h);
        __syncthreads();
        // FFN z: hidden = gelu(z @ w1^T + b1) -> s_h[0:128)
        gemm(s_z, ST, z_ffn_w1,            64, z_ffn_b1,      s_h, SH, 0,  1, tx, ty);
        gemm(s_z, ST, z_ffn_w1 + 64 * 64,  64, z_ffn_b1 + 64, s_h, SH, 64, 1, tx, ty);
        __syncthreads();
        // z += hidden @ w2^T + b2 ; LN(zn2)
        gemm(s_h, SH, z_ffn_w2, 128, z_ffn_b2, s_z, ST, 0, 2, tx, ty);
        __syncthreads();
        ln_row(s_z, ST, zn2_g, zn2_b, false, row, h);
        __syncthreads();
        // cross-attn: S0 = z2 @ Wvy^T + bvy ; y += S0 @ y_out_w^T + y_out_b ; LN(yn1)
        gemm(s_z, ST, Wvy, 64, bvy, s_h, SH, 0, 0, tx, ty);
        __syncthreads();
        gemm(s_h, SH, y_out_w, 64, y_out_b, s_y, ST, 0, 2, tx, ty);
        __syncthreads();
        ln_row(s_y, ST, yn1_g, yn1_b, false, row, h);
        __syncthreads();
        // FFN y
        gemm(s_y, ST, y_ffn_w1,            64, y_ffn_b1,      s_h, SH, 0,  1, tx, ty);
        gemm(s_y, ST, y_ffn_w1 + 64 * 64,  64, y_ffn_b1 + 64, s_h, SH, 64, 1, tx, ty);
        __syncthreads();
        gemm(s_h, SH, y_ffn_w2, 128, y_ffn_b2, s_y, ST, 0, 2, tx, ty);
        __syncthreads();
        ln_row(s_y, ST, yn2_g, yn2_b, false, row, h);
        __syncthreads();
    }

    // ---- output: (y @ W_out^T + b_out)[:, 0] ----
    {
        float acc = 0.f;
        const float* yp = s_y + row * ST + 32 * h;
#pragma unroll
        for (int j = 0; j < 32; j++) acc = fmaf(yp[j], __ldg(W_out + 32 * h + j), acc);
        acc += __shfl_xor_sync(0xFFFFFFFFu, acc, 1);
        if (h == 0 && row0 + row < Btotal) out[row0 + row] = acc + __ldg(b_out);
    }
}

extern "C" void kernel_launch(void* const* d_in, const int* in_sizes, int n_in,
                              void* d_out, int out_size)
{
    const float* x        = (const float*)d_in[0];
    const float* W_in     = (const float*)d_in[1];
    const float* b_in     = (const float*)d_in[2];
    const float* g_in     = (const float*)d_in[3];
    const float* be_in    = (const float*)d_in[4];
    const float* z_in_w   = (const float*)d_in[5];
    const float* z_in_b   = (const float*)d_in[6];
    const float* z_out_w  = (const float*)d_in[7];
    const float* z_out_b  = (const float*)d_in[8];
    const float* z_ffn_w1 = (const float*)d_in[9];
    const float* z_ffn_b1 = (const float*)d_in[10];
    const float* z_ffn_w2 = (const float*)d_in[11];
    const float* z_ffn_b2 = (const float*)d_in[12];
    const float* zn1_g    = (const float*)d_in[13];
    const float* zn1_b    = (const float*)d_in[14];
    const float* zn2_g    = (const float*)d_in[15];
    const float* zn2_b    = (const float*)d_in[16];
    const float* y_in_w   = (const float*)d_in[17];
    const float* y_in_b   = (const float*)d_in[18];
    const float* y_out_w  = (const float*)d_in[19];
    const float* y_out_b  = (const float*)d_in[20];
    const float* y_ffn_w1 = (const float*)d_in[21];
    const float* y_ffn_b1 = (const float*)d_in[22];
    const float* y_ffn_w2 = (const float*)d_in[23];
    const float* y_ffn_b2 = (const float*)d_in[24];
    const float* yn1_g    = (const float*)d_in[25];
    const float* yn1_b    = (const float*)d_in[26];
    const float* yn2_g    = (const float*)d_in[27];
    const float* yn2_b    = (const float*)d_in[28];
    const float* W_out    = (const float*)d_in[29];
    const float* b_out    = (const float*)d_in[30];
    float* out = (float*)d_out;

    int B = in_sizes[0] / 200;
    size_t smem = (size_t)(4 * ROWS * ST + ROWS * SH) * sizeof(float);  // 104448 B
    cudaFuncSetAttribute(trm_kernel, cudaFuncAttributeMaxDynamicSharedMemorySize, (int)smem);

    dim3 grid((B + ROWS - 1) / ROWS);
    trm_kernel<<<grid, TPB, smem>>>(x, W_in, b_in, g_in, be_in,
                                    z_in_w, z_in_b, z_out_w, z_out_b,
                                    z_ffn_w1, z_ffn_b1, z_ffn_w2, z_ffn_b2,
                                    zn1_g, zn1_b, zn2_g, zn2_b,
                                    y_in_w, y_in_b, y_out_w, y_out_b,
                                    y_ffn_w1, y_ffn_b1, y_ffn_w2, y_ffn_b2,
                                    yn1_g, yn1_b, yn2_g, yn2_b,
                                    W_out, b_out, out, B);
}

// round 8
// speedup vs baseline: 2.7819x; 2.0382x over previous
#include <cuda_runtime.h>

#define TPB    128
#define ROWS   64
#define ST     68          // buffer row stride in floats (68 % 32 == 4 -> conflict-free)
#define NSTEPS 16

__device__ __forceinline__ float gelu_exact(float v) {
    return 0.5f * v * (1.0f + erff(v * 0.70710678118654752f));
}

// ---------------------------------------------------------------------------
// gemm32: ONE WARP computes rows 0..63 x cols [32ch, 32ch+32) of
//   out = in(64 x 64, stride ST) @ W^T + bias      (W rows are 64-float, contiguous)
// lane: ly = lane&7 (rows ly+8i), lx = lane>>3 (cols 32ch + 8lx + j, j<8)
// 8x8 per-lane register tile -> 1.0 B writeback / FMA.
// mode: 0 = store, 1 = gelu+store, 2 = add into existing dest.
// ---------------------------------------------------------------------------
__device__ __forceinline__ void gemm32(const float* sIn, const float* __restrict__ W,
                                       const float* __restrict__ bias, float* sOut,
                                       int mode, int ch, int lane)
{
    const int ly = lane & 7, lx = lane >> 3;
    const int c0 = 32 * ch + 8 * lx;
    float acc[8][8];
#pragma unroll
    for (int i = 0; i < 8; i++)
#pragma unroll
        for (int j = 0; j < 8; j++) acc[i][j] = 0.f;

    const float* ip = sIn + ly * ST;
    const float* wp = W + c0 * 64;

#pragma unroll 1
    for (int k = 0; k < 64; k += 4) {
        float4 w[8];
#pragma unroll
        for (int j = 0; j < 8; j++) w[j] = __ldg((const float4*)(wp + j * 64 + k));
#pragma unroll
        for (int i = 0; i < 8; i++) {
            float4 b = *(const float4*)(ip + i * (8 * ST) + k);
#pragma unroll
            for (int j = 0; j < 8; j++)
                acc[i][j] = fmaf(b.x, w[j].x, fmaf(b.y, w[j].y,
                            fmaf(b.z, w[j].z, fmaf(b.w, w[j].w, acc[i][j]))));
        }
    }

    float bb[8];
    if (bias) {
#pragma unroll
        for (int j = 0; j < 8; j++) bb[j] = __ldg(bias + c0 + j);
    } else {
#pragma unroll
        for (int j = 0; j < 8; j++) bb[j] = 0.f;
    }
#pragma unroll
    for (int i = 0; i < 8; i++) {
        float* op = sOut + (ly + 8 * i) * ST + c0;
#pragma unroll
        for (int q = 0; q < 2; q++) {
            float4 v;
            v.x = acc[i][4*q+0] + bb[4*q+0]; v.y = acc[i][4*q+1] + bb[4*q+1];
            v.z = acc[i][4*q+2] + bb[4*q+2]; v.w = acc[i][4*q+3] + bb[4*q+3];
            if (mode == 1) {
                v.x = gelu_exact(v.x); v.y = gelu_exact(v.y);
                v.z = gelu_exact(v.z); v.w = gelu_exact(v.w);
            } else if (mode == 2) {
                float4 d = *(const float4*)(op + 4*q);
                v.x += d.x; v.y += d.y; v.z += d.z; v.w += d.w;
            }
            *(float4*)(op + 4*q) = v;
        }
    }
}

// ---------------------------------------------------------------------------
// gemm16: 4-WARP single unit; warp w computes cols [16w, 16w+16).
// lane: ly = lane&7 (rows ly+8i), lx = (lane>>3)&3 (cols 16w + 4lx).
// W row stride wrs, k-offset kof (for the FF=128 second half).
// ---------------------------------------------------------------------------
__device__ __forceinline__ void gemm16(const float* sIn, const float* __restrict__ W,
                                       int wrs, int kof,
                                       const float* __restrict__ bias, float* sOut,
                                       int mode, int w, int lane)
{
    const int ly = lane & 7, lx = (lane >> 3) & 3;
    const int c0 = 16 * w + 4 * lx;
    float acc[8][4];
#pragma unroll
    for (int i = 0; i < 8; i++)
#pragma unroll
        for (int j = 0; j < 4; j++) acc[i][j] = 0.f;

    const float* ip = sIn + ly * ST;
    const float* wp = W + c0 * wrs + kof;

#pragma unroll 1
    for (int k = 0; k < 64; k += 4) {
        float4 w4[4];
#pragma unroll
        for (int j = 0; j < 4; j++) w4[j] = __ldg((const float4*)(wp + j * wrs + k));
#pragma unroll
        for (int i = 0; i < 8; i++) {
            float4 b = *(const float4*)(ip + i * (8 * ST) + k);
#pragma unroll
            for (int j = 0; j < 4; j++)
                acc[i][j] = fmaf(b.x, w4[j].x, fmaf(b.y, w4[j].y,
                            fmaf(b.z, w4[j].z, fmaf(b.w, w4[j].w, acc[i][j]))));
        }
    }

    float4 bb;
    if (bias) bb = __ldg((const float4*)(bias + c0));
    else      bb = make_float4(0.f, 0.f, 0.f, 0.f);
#pragma unroll
    for (int i = 0; i < 8; i++) {
        float* op = sOut + (ly + 8 * i) * ST + c0;
        float4 v;
        v.x = acc[i][0] + bb.x; v.y = acc[i][1] + bb.y;
        v.z = acc[i][2] + bb.z; v.w = acc[i][3] + bb.w;
        if (mode == 1) {
            v.x = gelu_exact(v.x); v.y = gelu_exact(v.y);
            v.z = gelu_exact(v.z); v.w = gelu_exact(v.w);
        } else if (mode == 2) {
            float4 d = *(const float4*)op;
            v.x += d.x; v.y += d.y; v.z += d.z; v.w += d.w;
        }
        *(float4*)op = v;
    }
}

// Prologue: 4-warp, K=200, input rows from GLOBAL x (row stride 200).
__device__ __forceinline__ void gemm200(const float* __restrict__ gIn,
                                        const float* __restrict__ W,
                                        const float* __restrict__ bias, float* sOut,
                                        int w, int lane)
{
    const int ly = lane & 7, lx = (lane >> 3) & 3;
    const int c0 = 16 * w + 4 * lx;
    float acc[8][4];
#pragma unroll
    for (int i = 0; i < 8; i++)
#pragma unroll
        for (int j = 0; j < 4; j++) acc[i][j] = 0.f;

    const float* ip = gIn + (size_t)ly * 200;
    const float* wp = W + c0 * 200;

#pragma unroll 1
    for (int k = 0; k < 200; k += 4) {
        float4 w4[4];
#pragma unroll
        for (int j = 0; j < 4; j++) w4[j] = __ldg((const float4*)(wp + j * 200 + k));
#pragma unroll
        for (int i = 0; i < 8; i++) {
            float4 b = __ldg((const float4*)(ip + (size_t)i * 8 * 200 + k));
#pragma unroll
            for (int j = 0; j < 4; j++)
                acc[i][j] = fmaf(b.x, w4[j].x, fmaf(b.y, w4[j].y,
                            fmaf(b.z, w4[j].z, fmaf(b.w, w4[j].w, acc[i][j]))));
        }
    }
    float4 bb = __ldg((const float4*)(bias + c0));
#pragma unroll
    for (int i = 0; i < 8; i++) {
        float* op = sOut + (ly + 8 * i) * ST + c0;
        float4 v;
        v.x = acc[i][0] + bb.x; v.y = acc[i][1] + bb.y;
        v.z = acc[i][2] + bb.z; v.w = acc[i][3] + bb.w;
        *(float4*)op = v;
    }
}

// LayerNorm of one 64-float row held at p (single thread), optional gelu.
__device__ __forceinline__ void ln_row64(float* p, const float* __restrict__ g,
                                         const float* __restrict__ b, bool dogelu)
{
    float4 v[16];
#pragma unroll
    for (int i = 0; i < 16; i++) v[i] = *(const float4*)(p + 4 * i);
    float s = 0.f;
#pragma unroll
    for (int i = 0; i < 16; i++) s += (v[i].x + v[i].y) + (v[i].z + v[i].w);
    float m = s * (1.0f / 64.0f);
    float qv = 0.f;
#pragma unroll
    for (int i = 0; i < 16; i++) {
        float dx = v[i].x - m, dy = v[i].y - m, dz = v[i].z - m, dw = v[i].w - m;
        qv = fmaf(dx, dx, qv); qv = fmaf(dy, dy, qv);
        qv = fmaf(dz, dz, qv); qv = fmaf(dw, dw, qv);
    }
    float inv = rsqrtf(qv * (1.0f / 64.0f) + 1e-5f);
#pragma unroll
    for (int i = 0; i < 16; i++) {
        float4 gg = __ldg((const float4*)(g + 4 * i));
        float4 bb = __ldg((const float4*)(b + 4 * i));
        float4 r;
        r.x = fmaf((v[i].x - m) * inv, gg.x, bb.x);
        r.y = fmaf((v[i].y - m) * inv, gg.y, bb.y);
        r.z = fmaf((v[i].z - m) * inv, gg.z, bb.z);
        r.w = fmaf((v[i].w - m) * inv, gg.w, bb.w);
        if (dogelu) {
            r.x = gelu_exact(r.x); r.y = gelu_exact(r.y);
            r.z = gelu_exact(r.z); r.w = gelu_exact(r.w);
        }
        *(float4*)(p + 4 * i) = r;
    }
}

// pair-phase macro: warps 0,1 -> unit A (col halves 0/1); warps 2,3 -> unit B.
#define PAIR(inA, WA, bA, oA, mA, inB, WB, bB, oB, mB) do {            \
    const float* gi; const float* gw; const float* gb; float* go; int gm; \
    if (wid < 2) { gi = (inA); gw = (WA); gb = (bA); go = (oA); gm = (mA); } \
    else         { gi = (inB); gw = (WB); gb = (bB); go = (oB); gm = (mB); } \
    gemm32(gi, gw, gb, go, gm, wid & 1, lane);                          \
    __syncthreads(); } while (0)

#define SINGLE(in, W, wrs, kof, b, o, m) do {                          \
    gemm16((in), (W), (wrs), (kof), (b), (o), (m), wid, lane);         \
    __syncthreads(); } while (0)

__global__ void __launch_bounds__(TPB, 2)
trm_kernel(const float* __restrict__ x,
           const float* __restrict__ W_in,     const float* __restrict__ b_in,
           const float* __restrict__ g_in,     const float* __restrict__ be_in,
           const float* __restrict__ z_in_w,   const float* __restrict__ z_in_b,
           const float* __restrict__ z_out_w,  const float* __restrict__ z_out_b,
           const float* __restrict__ z_ffn_w1, const float* __restrict__ z_ffn_b1,
           const float* __restrict__ z_ffn_w2, const float* __restrict__ z_ffn_b2,
           const float* __restrict__ zn1_g,    const float* __restrict__ zn1_b,
           const float* __restrict__ zn2_g,    const float* __restrict__ zn2_b,
           const float* __restrict__ y_in_w,   const float* __restrict__ y_in_b,
           const float* __restrict__ y_out_w,  const float* __restrict__ y_out_b,
           const float* __restrict__ y_ffn_w1, const float* __restrict__ y_ffn_b1,
           const float* __restrict__ y_ffn_w2, const float* __restrict__ y_ffn_b2,
           const float* __restrict__ yn1_g,    const float* __restrict__ yn1_b,
           const float* __restrict__ yn2_g,    const float* __restrict__ yn2_b,
           const float* __restrict__ W_out,    const float* __restrict__ b_out,
           float* __restrict__ out, int Btotal)
{
    extern __shared__ float sm[];
    float* sKX = sm + 0 * ROWS * ST;
    float* sVX = sm + 1 * ROWS * ST;
    float* sY  = sm + 2 * ROWS * ST;
    float* sZ  = sm + 3 * ROWS * ST;
    float* sSA = sm + 4 * ROWS * ST;
    float* sSB = sm + 5 * ROWS * ST;

    const int tid  = threadIdx.x;
    const int wid  = tid >> 5;
    const int lane = tid & 31;
    const int row0 = blockIdx.x * ROWS;

    const float* Wq = z_in_w;
    const float* Wk = z_in_w + 64 * 64;
    const float* Wv = z_in_w + 128 * 64;
    const float* bq = z_in_b;
    const float* bk = z_in_b + 64;
    const float* bv = z_in_b + 128;
    const float* Wvy = y_in_w + 128 * 64;
    const float* bvy = y_in_b + 128;

    // row-thread persistent attention state (threads 0..63)
    float s0[4], s2[4], wa0[4], wa1[4], wa2[4];

    // ---- prologue: x_proj = gelu(LN(x @ W_in^T + b_in)) -> SA ----
    gemm200(x + (size_t)row0 * 200, W_in, b_in, sSA, wid, lane);
    __syncthreads();
    if (tid < 64) ln_row64(sSA + tid * ST, g_in, be_in, true);
    __syncthreads();
    // kx = xp@Wk^T+bk  ||  vx = xp@Wv^T+bv
    PAIR(sSA, Wk, bk, sKX, 0,  sSA, Wv, bv, sVX, 0);
    // zero y, z
    if (tid < 64) {
        float* yp = sY + tid * ST;
        float* zp = sZ + tid * ST;
        const float4 zz = make_float4(0.f, 0.f, 0.f, 0.f);
#pragma unroll
        for (int i = 0; i < 16; i++) { *(float4*)(yp + 4*i) = zz; *(float4*)(zp + 4*i) = zz; }
    }
    __syncthreads();

    // ---- 16 recursion steps ----
#pragma unroll 1
    for (int s = 0; s < NSTEPS; s++) {
        // P1: q(z) -> SA  ||  k(z) -> SB
        PAIR(sZ, Wq, bq, sSA, 0,  sZ, Wk, bk, sSB, 0);
        // E1: s0 = q.kx, s2 = q.kz (per head)
        if (tid < 64) {
            const float* qp  = sSA + tid * ST;
            const float* kxp = sKX + tid * ST;
            const float* kzp = sSB + tid * ST;
            float q[64];
#pragma unroll
            for (int i = 0; i < 16; i++) {
                float4 t = *(const float4*)(qp + 4*i);
                q[4*i] = t.x; q[4*i+1] = t.y; q[4*i+2] = t.z; q[4*i+3] = t.w;
            }
#pragma unroll
            for (int hh = 0; hh < 4; hh++) { s0[hh] = 0.f; s2[hh] = 0.f; }
#pragma unroll
            for (int i = 0; i < 16; i++) {
                int hh = i >> 2;
                float4 a = *(const float4*)(kxp + 4*i);
                float4 c = *(const float4*)(kzp + 4*i);
                s0[hh] = fmaf(q[4*i], a.x, fmaf(q[4*i+1], a.y,
                         fmaf(q[4*i+2], a.z, fmaf(q[4*i+3], a.w, s0[hh]))));
                s2[hh] = fmaf(q[4*i], c.x, fmaf(q[4*i+1], c.y,
                         fmaf(q[4*i+2], c.z, fmaf(q[4*i+3], c.w, s2[hh]))));
            }
        }
        __syncthreads();
        // P2: k(y) -> SB (single; SA=q preserved)
        SINGLE(sY, Wk, 64, 0, bk, sSB, 0);
        // E2: s1 = q.ky ; softmax -> wa0/1/2
        if (tid < 64) {
            const float* qp  = sSA + tid * ST;
            const float* kyp = sSB + tid * ST;
            float q[64];
#pragma unroll
            for (int i = 0; i < 16; i++) {
                float4 t = *(const float4*)(qp + 4*i);
                q[4*i] = t.x; q[4*i+1] = t.y; q[4*i+2] = t.z; q[4*i+3] = t.w;
            }
            float s1[4] = {0.f, 0.f, 0.f, 0.f};
#pragma unroll
            for (int i = 0; i < 16; i++) {
                int hh = i >> 2;
                float4 a = *(const float4*)(kyp + 4*i);
                s1[hh] = fmaf(q[4*i], a.x, fmaf(q[4*i+1], a.y,
                         fmaf(q[4*i+2], a.z, fmaf(q[4*i+3], a.w, s1[hh]))));
            }
#pragma unroll
            for (int hh = 0; hh < 4; hh++) {
                float a0 = s0[hh] * 0.25f, a1 = s1[hh] * 0.25f, a2 = s2[hh] * 0.25f;
                float mx = fmaxf(a0, fmaxf(a1, a2));
                float e0 = expf(a0 - mx), e1 = expf(a1 - mx), e2 = expf(a2 - mx);
                float rs = 1.0f / (e0 + e1 + e2);
                wa0[hh] = e0 * rs; wa1[hh] = e1 * rs; wa2[hh] = e2 * rs;
            }
        }
        __syncthreads();
        // P3: v(y) -> SA  ||  v(z) -> SB
        PAIR(sY, Wv, bv, sSA, 0,  sZ, Wv, bv, sSB, 0);
        // E3: SA := wa0*vx + wa1*vy + wa2*vz
        if (tid < 64) {
            float* sap = sSA + tid * ST;
            const float* sbp = sSB + tid * ST;
            const float* vxp = sVX + tid * ST;
#pragma unroll
            for (int i = 0; i < 16; i++) {
                int hh = i >> 2;
                float4 a = *(const float4*)(vxp + 4*i);
                float4 b2 = *(const float4*)(sap + 4*i);
                float4 c = *(const float4*)(sbp + 4*i);
                float4 o;
                o.x = wa0[hh]*a.x + wa1[hh]*b2.x + wa2[hh]*c.x;
                o.y = wa0[hh]*a.y + wa1[hh]*b2.y + wa2[hh]*c.y;
                o.z = wa0[hh]*a.z + wa1[hh]*b2.z + wa2[hh]*c.z;
                o.w = wa0[hh]*a.w + wa1[hh]*b2.w + wa2[hh]*c.w;
                *(float4*)(sap + 4*i) = o;
            }
        }
        __syncthreads();
        // P4: z += SA @ z_out_w^T + z_out_b ; LN zn1
        SINGLE(sSA, z_out_w, 64, 0, z_out_b, sZ, 2);
        if (tid < 64) ln_row64(sZ + tid * ST, zn1_g, zn1_b, false);
        __syncthreads();
        // P5: FFN z hidden: gelu -> SA (rows 0-63) || SB (rows 64-127)
        PAIR(sZ, z_ffn_w1, z_ffn_b1, sSA, 1,  sZ, z_ffn_w1 + 64*64, z_ffn_b1 + 64, sSB, 1);
        // P6: z += [SA|SB] @ w2^T + b2 ; LN zn2
        gemm16(sSA, z_ffn_w2, 128, 0,  z_ffn_b2, sZ, 2, wid, lane);
        gemm16(sSB, z_ffn_w2, 128, 64, (const float*)0, sZ, 2, wid, lane);
        __syncthreads();
        if (tid < 64) ln_row64(sZ + tid * ST, zn2_g, zn2_b, false);
        __syncthreads();
        // P7: ca1: SA = z2 @ Wvy^T + bvy
        SINGLE(sZ, Wvy, 64, 0, bvy, sSA, 0);
        // P8: y += SA @ y_out_w^T + y_out_b ; LN yn1
        SINGLE(sSA, y_out_w, 64, 0, y_out_b, sY, 2);
        if (tid < 64) ln_row64(sY + tid * ST, yn1_g, yn1_b, false);
        __syncthreads();
        // P9: FFN y hidden
        PAIR(sY, y_ffn_w1, y_ffn_b1, sSA, 1,  sY, y_ffn_w1 + 64*64, y_ffn_b1 + 64, sSB, 1);
        // P10: y += [SA|SB] @ w2^T + b2 ; LN yn2
        gemm16(sSA, y_ffn_w2, 128, 0,  y_ffn_b2, sY, 2, wid, lane);
        gemm16(sSB, y_ffn_w2, 128, 64, (const float*)0, sY, 2, wid, lane);
        __syncthreads();
        if (tid < 64) ln_row64(sY + tid * ST, yn2_g, yn2_b, false);
        __syncthreads();
    }

    // ---- output: (y @ W_out^T + b_out)[:, 0] ----
    if (tid < 64) {
        const float* yp = sY + tid * ST;
        float acc = __ldg(b_out);
#pragma unroll
        for (int i = 0; i < 16; i++) {
            float4 v = *(const float4*)(yp + 4*i);
            float4 w = __ldg((const float4*)(W_out + 4*i));
            acc = fmaf(v.x, w.x, fmaf(v.y, w.y, fmaf(v.z, w.z, fmaf(v.w, w.w, acc))));
        }
        int r = row0 + tid;
        if (r < Btotal) out[r] = acc;
    }
}

extern "C" void kernel_launch(void* const* d_in, const int* in_sizes, int n_in,
                              void* d_out, int out_size)
{
    const float* x        = (const float*)d_in[0];
    const float* W_in     = (const float*)d_in[1];
    const float* b_in     = (const float*)d_in[2];
    const float* g_in     = (const float*)d_in[3];
    const float* be_in    = (const float*)d_in[4];
    const float* z_in_w   = (const float*)d_in[5];
    const float* z_in_b   = (const float*)d_in[6];
    const float* z_out_w  = (const float*)d_in[7];
    const float* z_out_b  = (const float*)d_in[8];
    const float* z_ffn_w1 = (const float*)d_in[9];
    const float* z_ffn_b1 = (const float*)d_in[10];
    const float* z_ffn_w2 = (const float*)d_in[11];
    const float* z_ffn_b2 = (const float*)d_in[12];
    const float* zn1_g    = (const float*)d_in[13];
    const float* zn1_b    = (const float*)d_in[14];
    const float* zn2_g    = (const float*)d_in[15];
    const float* zn2_b    = (const float*)d_in[16];
    const float* y_in_w   = (const float*)d_in[17];
    const float* y_in_b   = (const float*)d_in[18];
    const float* y_out_w  = (const float*)d_in[19];
    const float* y_out_b  = (const float*)d_in[20];
    const float* y_ffn_w1 = (const float*)d_in[21];
    const float* y_ffn_b1 = (const float*)d_in[22];
    const float* y_ffn_w2 = (const float*)d_in[23];
    const float* y_ffn_b2 = (const float*)d_in[24];
    const float* yn1_g    = (const float*)d_in[25];
    const float* yn1_b    = (const float*)d_in[26];
    const float* yn2_g    = (const float*)d_in[27];
    const float* yn2_b    = (const float*)d_in[28];
    const float* W_out    = (const float*)d_in[29];
    const float* b_out    = (const float*)d_in[30];
    float* out = (float*)d_out;

    int B = in_sizes[0] / 200;
    size_t smem = (size_t)6 * ROWS * ST * sizeof(float);   // 104448 B -> 2 CTAs/SM
    cudaFuncSetAttribute(trm_kernel, cudaFuncAttributeMaxDynamicSharedMemorySize, (int)smem);

    dim3 grid((B + ROWS - 1) / ROWS);
    trm_kernel<<<grid, TPB, smem>>>(x, W_in, b_in, g_in, be_in,
                                    z_in_w, z_in_b, z_out_w, z_out_b,
                                    z_ffn_w1, z_ffn_b1, z_ffn_w2, z_ffn_b2,
                                    zn1_g, zn1_b, zn2_g, zn2_b,
                                    y_in_w, y_in_b, y_out_w, y_out_b,
                                    y_ffn_w1, y_ffn_b1, y_ffn_w2, y_ffn_b2,
                                    yn1_g, yn1_b, yn2_g, yn2_b,
                                    W_out, b_out, out, B);
}

// round 9
// speedup vs baseline: 3.1655x; 1.1379x over previous
#include <cuda_runtime.h>

#define TPB    128
#define ROWS   64
#define ST     68          // buffer row stride in floats (68 % 32 == 4 -> conflict-free)
#define NSTEPS 16

__device__ __forceinline__ float gelu_exact(float v) {
    return 0.5f * v * (1.0f + erff(v * 0.70710678118654752f));
}

// packed fp32x2 FMA: acc.{lo,hi} += a.{lo,hi} * b.{lo,hi}   (FFMA2 on sm_103a)
__device__ __forceinline__ void ffma2(unsigned long long& acc,
                                      unsigned long long a, unsigned long long b) {
    asm("fma.rn.f32x2 %0, %1, %2, %0;" : "+l"(acc) : "l"(a), "l"(b));
}
// horizontal reduce of a packed pair
__device__ __forceinline__ float pairsum(unsigned long long v) {
    float lo, hi;
    asm("mov.b64 {%0, %1}, %2;" : "=f"(lo), "=f"(hi) : "l"(v));
    return lo + hi;
}

// ---------------------------------------------------------------------------
// gemm32: ONE WARP computes rows 0..63 x cols [32ch, 32ch+32) of
//   out = in(64 x 64, stride ST) @ W^T + bias      (W rows 64-float contiguous)
// lane: ly = lane&7 (rows ly+8i), lx = lane>>3 (cols 32ch + 8lx + j).
// 8x8 per-lane tile, k-packed FFMA2 accumulators (acc.lo = even k, .hi = odd k).
// mode: 0 = store, 1 = gelu+store, 2 = add into existing dest.
// ---------------------------------------------------------------------------
__device__ __forceinline__ void gemm32(const float* sIn, const float* __restrict__ W,
                                       const float* __restrict__ bias, float* sOut,
                                       int mode, int ch, int lane)
{
    const int ly = lane & 7, lx = lane >> 3;
    const int c0 = 32 * ch + 8 * lx;
    unsigned long long acc[8][8];
#pragma unroll
    for (int i = 0; i < 8; i++)
#pragma unroll
        for (int j = 0; j < 8; j++) acc[i][j] = 0ull;

    const float* ip = sIn + ly * ST;
    const float* wp = W + c0 * 64;

#pragma unroll 1
    for (int k = 0; k < 64; k += 4) {
        ulonglong2 w[8];
#pragma unroll
        for (int j = 0; j < 8; j++) w[j] = __ldg((const ulonglong2*)(wp + j * 64 + k));
#pragma unroll
        for (int i = 0; i < 8; i++) {
            ulonglong2 b = *(const ulonglong2*)(ip + i * (8 * ST) + k);
#pragma unroll
            for (int j = 0; j < 8; j++) {
                ffma2(acc[i][j], w[j].x, b.x);
                ffma2(acc[i][j], w[j].y, b.y);
            }
        }
    }

    float bb[8];
    if (bias) {
#pragma unroll
        for (int j = 0; j < 8; j++) bb[j] = __ldg(bias + c0 + j);
    } else {
#pragma unroll
        for (int j = 0; j < 8; j++) bb[j] = 0.f;
    }
#pragma unroll
    for (int i = 0; i < 8; i++) {
        float* op = sOut + (ly + 8 * i) * ST + c0;
#pragma unroll
        for (int q = 0; q < 2; q++) {
            float4 v;
            v.x = pairsum(acc[i][4*q+0]) + bb[4*q+0];
            v.y = pairsum(acc[i][4*q+1]) + bb[4*q+1];
            v.z = pairsum(acc[i][4*q+2]) + bb[4*q+2];
            v.w = pairsum(acc[i][4*q+3]) + bb[4*q+3];
            if (mode == 1) {
                v.x = gelu_exact(v.x); v.y = gelu_exact(v.y);
                v.z = gelu_exact(v.z); v.w = gelu_exact(v.w);
            } else if (mode == 2) {
                float4 d = *(const float4*)(op + 4*q);
                v.x += d.x; v.y += d.y; v.z += d.z; v.w += d.w;
            }
            *(float4*)(op + 4*q) = v;
        }
    }
}

// ---------------------------------------------------------------------------
// gemm16: 4-WARP single unit; warp w computes cols [16w, 16w+16).
// lane: ly = lane&7 (rows ly+8i), lx = (lane>>3)&3 (cols 16w + 4lx).
// ---------------------------------------------------------------------------
__device__ __forceinline__ void gemm16(const float* sIn, const float* __restrict__ W,
                                       int wrs, int kof,
                                       const float* __restrict__ bias, float* sOut,
                                       int mode, int w, int lane)
{
    const int ly = lane & 7, lx = (lane >> 3) & 3;
    const int c0 = 16 * w + 4 * lx;
    unsigned long long acc[8][4];
#pragma unroll
    for (int i = 0; i < 8; i++)
#pragma unroll
        for (int j = 0; j < 4; j++) acc[i][j] = 0ull;

    const float* ip = sIn + ly * ST;
    const float* wp = W + c0 * wrs + kof;

#pragma unroll 1
    for (int k = 0; k < 64; k += 4) {
        ulonglong2 w4[4];
#pragma unroll
        for (int j = 0; j < 4; j++) w4[j] = __ldg((const ulonglong2*)(wp + j * wrs + k));
#pragma unroll
        for (int i = 0; i < 8; i++) {
            ulonglong2 b = *(const ulonglong2*)(ip + i * (8 * ST) + k);
#pragma unroll
            for (int j = 0; j < 4; j++) {
                ffma2(acc[i][j], w4[j].x, b.x);
                ffma2(acc[i][j], w4[j].y, b.y);
            }
        }
    }

    float4 bb;
    if (bias) bb = __ldg((const float4*)(bias + c0));
    else      bb = make_float4(0.f, 0.f, 0.f, 0.f);
#pragma unroll
    for (int i = 0; i < 8; i++) {
        float* op = sOut + (ly + 8 * i) * ST + c0;
        float4 v;
        v.x = pairsum(acc[i][0]) + bb.x; v.y = pairsum(acc[i][1]) + bb.y;
        v.z = pairsum(acc[i][2]) + bb.z; v.w = pairsum(acc[i][3]) + bb.w;
        if (mode == 1) {
            v.x = gelu_exact(v.x); v.y = gelu_exact(v.y);
            v.z = gelu_exact(v.z); v.w = gelu_exact(v.w);
        } else if (mode == 2) {
            float4 d = *(const float4*)op;
            v.x += d.x; v.y += d.y; v.z += d.z; v.w += d.w;
        }
        *(float4*)op = v;
    }
}

// Prologue: 4-warp, K=200, input rows from GLOBAL x (row stride 200).
__device__ __forceinline__ void gemm200(const float* __restrict__ gIn,
                                        const float* __restrict__ W,
                                        const float* __restrict__ bias, float* sOut,
                                        int w, int lane)
{
    const int ly = lane & 7, lx = (lane >> 3) & 3;
    const int c0 = 16 * w + 4 * lx;
    unsigned long long acc[8][4];
#pragma unroll
    for (int i = 0; i < 8; i++)
#pragma unroll
        for (int j = 0; j < 4; j++) acc[i][j] = 0ull;

    const float* ip = gIn + (size_t)ly * 200;
    const float* wp = W + c0 * 200;

#pragma unroll 1
    for (int k = 0; k < 200; k += 4) {
        ulonglong2 w4[4];
#pragma unroll
        for (int j = 0; j < 4; j++) w4[j] = __ldg((const ulonglong2*)(wp + j * 200 + k));
#pragma unroll
        for (int i = 0; i < 8; i++) {
            ulonglong2 b = __ldg((const ulonglong2*)(ip + (size_t)i * 8 * 200 + k));
#pragma unroll
            for (int j = 0; j < 4; j++) {
                ffma2(acc[i][j], w4[j].x, b.x);
                ffma2(acc[i][j], w4[j].y, b.y);
            }
        }
    }
    float4 bb = __ldg((const float4*)(bias + c0));
#pragma unroll
    for (int i = 0; i < 8; i++) {
        float* op = sOut + (ly + 8 * i) * ST + c0;
        float4 v;
        v.x = pairsum(acc[i][0]) + bb.x; v.y = pairsum(acc[i][1]) + bb.y;
        v.z = pairsum(acc[i][2]) + bb.z; v.w = pairsum(acc[i][3]) + bb.w;
        *(float4*)op = v;
    }
}

// LayerNorm of one 64-float row held at p (single thread), optional gelu.
__device__ __forceinline__ void ln_row64(float* p, const float* __restrict__ g,
                                         const float* __restrict__ b, bool dogelu)
{
    float4 v[16];
#pragma unroll
    for (int i = 0; i < 16; i++) v[i] = *(const float4*)(p + 4 * i);
    float s = 0.f;
#pragma unroll
    for (int i = 0; i < 16; i++) s += (v[i].x + v[i].y) + (v[i].z + v[i].w);
    float m = s * (1.0f / 64.0f);
    float qv = 0.f;
#pragma unroll
    for (int i = 0; i < 16; i++) {
        float dx = v[i].x - m, dy = v[i].y - m, dz = v[i].z - m, dw = v[i].w - m;
        qv = fmaf(dx, dx, qv); qv = fmaf(dy, dy, qv);
        qv = fmaf(dz, dz, qv); qv = fmaf(dw, dw, qv);
    }
    float inv = rsqrtf(qv * (1.0f / 64.0f) + 1e-5f);
#pragma unroll
    for (int i = 0; i < 16; i++) {
        float4 gg = __ldg((const float4*)(g + 4 * i));
        float4 bb = __ldg((const float4*)(b + 4 * i));
        float4 r;
        r.x = fmaf((v[i].x - m) * inv, gg.x, bb.x);
        r.y = fmaf((v[i].y - m) * inv, gg.y, bb.y);
        r.z = fmaf((v[i].z - m) * inv, gg.z, bb.z);
        r.w = fmaf((v[i].w - m) * inv, gg.w, bb.w);
        if (dogelu) {
            r.x = gelu_exact(r.x); r.y = gelu_exact(r.y);
            r.z = gelu_exact(r.z); r.w = gelu_exact(r.w);
        }
        *(float4*)(p + 4 * i) = r;
    }
}

// pair-phase macro: warps 0,1 -> unit A (col halves 0/1); warps 2,3 -> unit B.
#define PAIR(inA, WA, bA, oA, mA, inB, WB, bB, oB, mB) do {            \
    const float* gi; const float* gw; const float* gb; float* go; int gm; \
    if (wid < 2) { gi = (inA); gw = (WA); gb = (bA); go = (oA); gm = (mA); } \
    else         { gi = (inB); gw = (WB); gb = (bB); go = (oB); gm = (mB); } \
    gemm32(gi, gw, gb, go, gm, wid & 1, lane);                          \
    __syncthreads(); } while (0)

#define SINGLE(in, W, wrs, kof, b, o, m) do {                          \
    gemm16((in), (W), (wrs), (kof), (b), (o), (m), wid, lane);         \
    __syncthreads(); } while (0)

__global__ void __launch_bounds__(TPB, 2)
trm_kernel(const float* __restrict__ x,
           const float* __restrict__ W_in,     const float* __restrict__ b_in,
           const float* __restrict__ g_in,     const float* __restrict__ be_in,
           const float* __restrict__ z_in_w,   const float* __restrict__ z_in_b,
           const float* __restrict__ z_out_w,  const float* __restrict__ z_out_b,
           const float* __restrict__ z_ffn_w1, const float* __restrict__ z_ffn_b1,
           const float* __restrict__ z_ffn_w2, const float* __restrict__ z_ffn_b2,
           const float* __restrict__ zn1_g,    const float* __restrict__ zn1_b,
           const float* __restrict__ zn2_g,    const float* __restrict__ zn2_b,
           const float* __restrict__ y_in_w,   const float* __restrict__ y_in_b,
           const float* __restrict__ y_out_w,  const float* __restrict__ y_out_b,
           const float* __restrict__ y_ffn_w1, const float* __restrict__ y_ffn_b1,
           const float* __restrict__ y_ffn_w2, const float* __restrict__ y_ffn_b2,
           const float* __restrict__ yn1_g,    const float* __restrict__ yn1_b,
           const float* __restrict__ yn2_g,    const float* __restrict__ yn2_b,
           const float* __restrict__ W_out,    const float* __restrict__ b_out,
           float* __restrict__ out, int Btotal)
{
    extern __shared__ float sm[];
    float* sKX = sm + 0 * ROWS * ST;
    float* sVX = sm + 1 * ROWS * ST;
    float* sY  = sm + 2 * ROWS * ST;
    float* sZ  = sm + 3 * ROWS * ST;
    float* sSA = sm + 4 * ROWS * ST;
    float* sSB = sm + 5 * ROWS * ST;

    const int tid  = threadIdx.x;
    const int wid  = tid >> 5;
    const int lane = tid & 31;
    const int row0 = blockIdx.x * ROWS;

    const float* Wq = z_in_w;
    const float* Wk = z_in_w + 64 * 64;
    const float* Wv = z_in_w + 128 * 64;
    const float* bq = z_in_b;
    const float* bk = z_in_b + 64;
    const float* bv = z_in_b + 128;
    const float* Wvy = y_in_w + 128 * 64;
    const float* bvy = y_in_b + 128;

    // row-thread persistent attention state (threads 0..63)
    float s0[4], s2[4], wa0[4], wa1[4], wa2[4];

    // ---- prologue: x_proj = gelu(LN(x @ W_in^T + b_in)) -> SA ----
    gemm200(x + (size_t)row0 * 200, W_in, b_in, sSA, wid, lane);
    __syncthreads();
    if (tid < 64) ln_row64(sSA + tid * ST, g_in, be_in, true);
    __syncthreads();
    // kx = xp@Wk^T+bk  ||  vx = xp@Wv^T+bv
    PAIR(sSA, Wk, bk, sKX, 0,  sSA, Wv, bv, sVX, 0);
    // zero y, z
    if (tid < 64) {
        float* yp = sY + tid * ST;
        float* zp = sZ + tid * ST;
        const float4 zz = make_float4(0.f, 0.f, 0.f, 0.f);
#pragma unroll
        for (int i = 0; i < 16; i++) { *(float4*)(yp + 4*i) = zz; *(float4*)(zp + 4*i) = zz; }
    }
    __syncthreads();

    // ---- 16 recursion steps ----
#pragma unroll 1
    for (int s = 0; s < NSTEPS; s++) {
        // P1: q(z) -> SA  ||  k(z) -> SB
        PAIR(sZ, Wq, bq, sSA, 0,  sZ, Wk, bk, sSB, 0);
        // E1: s0 = q.kx, s2 = q.kz (per head)
        if (tid < 64) {
            const float* qp  = sSA + tid * ST;
            const float* kxp = sKX + tid * ST;
            const float* kzp = sSB + tid * ST;
            float q[64];
#pragma unroll
            for (int i = 0; i < 16; i++) {
                float4 t = *(const float4*)(qp + 4*i);
                q[4*i] = t.x; q[4*i+1] = t.y; q[4*i+2] = t.z; q[4*i+3] = t.w;
            }
#pragma unroll
            for (int hh = 0; hh < 4; hh++) { s0[hh] = 0.f; s2[hh] = 0.f; }
#pragma unroll
            for (int i = 0; i < 16; i++) {
                int hh = i >> 2;
                float4 a = *(const float4*)(kxp + 4*i);
                float4 c = *(const float4*)(kzp + 4*i);
                s0[hh] = fmaf(q[4*i], a.x, fmaf(q[4*i+1], a.y,
                         fmaf(q[4*i+2], a.z, fmaf(q[4*i+3], a.w, s0[hh]))));
                s2[hh] = fmaf(q[4*i], c.x, fmaf(q[4*i+1], c.y,
                         fmaf(q[4*i+2], c.z, fmaf(q[4*i+3], c.w, s2[hh]))));
            }
        }
        __syncthreads();
        // P2: k(y) -> SB (single; SA=q preserved)
        SINGLE(sY, Wk, 64, 0, bk, sSB, 0);
        // E2: s1 = q.ky ; softmax -> wa0/1/2
        if (tid < 64) {
            const float* qp  = sSA + tid * ST;
            const float* kyp = sSB + tid * ST;
            float q[64];
#pragma unroll
            for (int i = 0; i < 16; i++) {
                float4 t = *(const float4*)(qp + 4*i);
                q[4*i] = t.x; q[4*i+1] = t.y; q[4*i+2] = t.z; q[4*i+3] = t.w;
            }
            float s1[4] = {0.f, 0.f, 0.f, 0.f};
#pragma unroll
            for (int i = 0; i < 16; i++) {
                int hh = i >> 2;
                float4 a = *(const float4*)(kyp + 4*i);
                s1[hh] = fmaf(q[4*i], a.x, fmaf(q[4*i+1], a.y,
                         fmaf(q[4*i+2], a.z, fmaf(q[4*i+3], a.w, s1[hh]))));
            }
#pragma unroll
            for (int hh = 0; hh < 4; hh++) {
                float a0 = s0[hh] * 0.25f, a1 = s1[hh] * 0.25f, a2 = s2[hh] * 0.25f;
                float mx = fmaxf(a0, fmaxf(a1, a2));
                float e0 = expf(a0 - mx), e1 = expf(a1 - mx), e2 = expf(a2 - mx);
                float rs = 1.0f / (e0 + e1 + e2);
                wa0[hh] = e0 * rs; wa1[hh] = e1 * rs; wa2[hh] = e2 * rs;
            }
        }
        __syncthreads();
        // P3: v(y) -> SA  ||  v(z) -> SB
        PAIR(sY, Wv, bv, sSA, 0,  sZ, Wv, bv, sSB, 0);
        // E3: SA := wa0*vx + wa1*vy + wa2*vz
        if (tid < 64) {
            float* sap = sSA + tid * ST;
            const float* sbp = sSB + tid * ST;
            const float* vxp = sVX + tid * ST;
#pragma unroll
            for (int i = 0; i < 16; i++) {
                int hh = i >> 2;
                float4 a = *(const float4*)(vxp + 4*i);
                float4 b2 = *(const float4*)(sap + 4*i);
                float4 c = *(const float4*)(sbp + 4*i);
                float4 o;
                o.x = wa0[hh]*a.x + wa1[hh]*b2.x + wa2[hh]*c.x;
                o.y = wa0[hh]*a.y + wa1[hh]*b2.y + wa2[hh]*c.y;
                o.z = wa0[hh]*a.z + wa1[hh]*b2.z + wa2[hh]*c.z;
                o.w = wa0[hh]*a.w + wa1[hh]*b2.w + wa2[hh]*c.w;
                *(float4*)(sap + 4*i) = o;
            }
        }
        __syncthreads();
        // P4: z += SA @ z_out_w^T + z_out_b ; LN zn1
        SINGLE(sSA, z_out_w, 64, 0, z_out_b, sZ, 2);
        if (tid < 64) ln_row64(sZ + tid * ST, zn1_g, zn1_b, false);
        __syncthreads();
        // P5: FFN z hidden: gelu -> SA (rows 0-63) || SB (rows 64-127)
        PAIR(sZ, z_ffn_w1, z_ffn_b1, sSA, 1,  sZ, z_ffn_w1 + 64*64, z_ffn_b1 + 64, sSB, 1);
        // P6: z += [SA|SB] @ w2^T + b2 ; LN zn2
        gemm16(sSA, z_ffn_w2, 128, 0,  z_ffn_b2, sZ, 2, wid, lane);
        gemm16(sSB, z_ffn_w2, 128, 64, (const float*)0, sZ, 2, wid, lane);
        __syncthreads();
        if (tid < 64) ln_row64(sZ + tid * ST, zn2_g, zn2_b, false);
        __syncthreads();
        // P7: ca1: SA = z2 @ Wvy^T + bvy
        SINGLE(sZ, Wvy, 64, 0, bvy, sSA, 0);
        // P8: y += SA @ y_out_w^T + y_out_b ; LN yn1
        SINGLE(sSA, y_out_w, 64, 0, y_out_b, sY, 2);
        if (tid < 64) ln_row64(sY + tid * ST, yn1_g, yn1_b, false);
        __syncthreads();
        // P9: FFN y hidden
        PAIR(sY, y_ffn_w1, y_ffn_b1, sSA, 1,  sY, y_ffn_w1 + 64*64, y_ffn_b1 + 64, sSB, 1);
        // P10: y += [SA|SB] @ w2^T + b2 ; LN yn2
        gemm16(sSA, y_ffn_w2, 128, 0,  y_ffn_b2, sY, 2, wid, lane);
        gemm16(sSB, y_ffn_w2, 128, 64, (const float*)0, sY, 2, wid, lane);
        __syncthreads();
        if (tid < 64) ln_row64(sY + tid * ST, yn2_g, yn2_b, false);
        __syncthreads();
    }

    // ---- output: (y @ W_out^T + b_out)[:, 0] ----
    if (tid < 64) {
        const float* yp = sY + tid * ST;
        float acc = __ldg(b_out);
#pragma unroll
        for (int i = 0; i < 16; i++) {
            float4 v = *(const float4*)(yp + 4*i);
            float4 w = __ldg((const float4*)(W_out + 4*i));
            acc = fmaf(v.x, w.x, fmaf(v.y, w.y, fmaf(v.z, w.z, fmaf(v.w, w.w, acc))));
        }
        int r = row0 + tid;
        if (r < Btotal) out[r] = acc;
    }
}

extern "C" void kernel_launch(void* const* d_in, const int* in_sizes, int n_in,
                              void* d_out, int out_size)
{
    const float* x        = (const float*)d_in[0];
    const float* W_in     = (const float*)d_in[1];
    const float* b_in     = (const float*)d_in[2];
    const float* g_in     = (const float*)d_in[3];
    const float* be_in    = (const float*)d_in[4];
    const float* z_in_w   = (const float*)d_in[5];
    const float* z_in_b   = (const float*)d_in[6];
    const float* z_out_w  = (const float*)d_in[7];
    const float* z_out_b  = (const float*)d_in[8];
    const float* z_ffn_w1 = (const float*)d_in[9];
    const float* z_ffn_b1 = (const float*)d_in[10];
    const float* z_ffn_w2 = (const float*)d_in[11];
    const float* z_ffn_b2 = (const float*)d_in[12];
    const float* zn1_g    = (const float*)d_in[13];
    const float* zn1_b    = (const float*)d_in[14];
    const float* zn2_g    = (const float*)d_in[15];
    const float* zn2_b    = (const float*)d_in[16];
    const float* y_in_w   = (const float*)d_in[17];
    const float* y_in_b   = (const float*)d_in[18];
    const float* y_out_w  = (const float*)d_in[19];
    const float* y_out_b  = (const float*)d_in[20];
    const float* y_ffn_w1 = (const float*)d_in[21];
    const float* y_ffn_b1 = (const float*)d_in[22];
    const float* y_ffn_w2 = (const float*)d_in[23];
    const float* y_ffn_b2 = (const float*)d_in[24];
    const float* yn1_g    = (const float*)d_in[25];
    const float* yn1_b    = (const float*)d_in[26];
    const float* yn2_g    = (const float*)d_in[27];
    const float* yn2_b    = (const float*)d_in[28];
    const float* W_out    = (const float*)d_in[29];
    const float* b_out    = (const float*)d_in[30];
    float* out = (float*)d_out;

    int B = in_sizes[0] / 200;
    size_t smem = (size_t)6 * ROWS * ST * sizeof(float);   // 104448 B -> 2 CTAs/SM
    cudaFuncSetAttribute(trm_kernel, cudaFuncAttributeMaxDynamicSharedMemorySize, (int)smem);

    dim3 grid((B + ROWS - 1) / ROWS);
    trm_kernel<<<grid, TPB, smem>>>(x, W_in, b_in, g_in, be_in,
                                    z_in_w, z_in_b, z_out_w, z_out_b,
                                    z_ffn_w1, z_ffn_b1, z_ffn_w2, z_ffn_b2,
                                    zn1_g, zn1_b, zn2_g, zn2_b,
                                    y_in_w, y_in_b, y_out_w, y_out_b,
                                    y_ffn_w1, y_ffn_b1, y_ffn_w2, y_ffn_b2,
                                    yn1_g, yn1_b, yn2_g, yn2_b,
                                    W_out, b_out, out, B);
}

// round 10
// speedup vs baseline: 3.2232x; 1.0182x over previous
#include <cuda_runtime.h>

#define TPB    128
#define ROWS   64
#define ST     68          // buffer row stride in floats (68 % 32 == 4 -> conflict-free)
#define NSTEPS 16

__device__ __forceinline__ float gelu_exact(float v) {
    return 0.5f * v * (1.0f + erff(v * 0.70710678118654752f));
}

// packed fp32x2 FMA: acc.{lo,hi} += a.{lo,hi} * b.{lo,hi}   (FFMA2 on sm_103a)
__device__ __forceinline__ void ffma2(unsigned long long& acc,
                                      unsigned long long a, unsigned long long b) {
    asm("fma.rn.f32x2 %0, %1, %2, %0;" : "+l"(acc) : "l"(a), "l"(b));
}
// horizontal reduce of a packed pair
__device__ __forceinline__ float pairsum(unsigned long long v) {
    float lo, hi;
    asm("mov.b64 {%0, %1}, %2;" : "=f"(lo), "=f"(hi) : "l"(v));
    return lo + hi;
}

// ---------------------------------------------------------------------------
// gemm32: ONE WARP computes rows 0..63 x cols [32ch, 32ch+32); 8x8 per-lane
// tile, k-packed FFMA2 accumulators. mode: 0=store, 1=gelu+store, 2=add-dest.
// ---------------------------------------------------------------------------
__device__ __forceinline__ void gemm32(const float* sIn, const float* __restrict__ W,
                                       const float* __restrict__ bias, float* sOut,
                                       int mode, int ch, int lane)
{
    const int ly = lane & 7, lx = lane >> 3;
    const int c0 = 32 * ch + 8 * lx;
    unsigned long long acc[8][8];
#pragma unroll
    for (int i = 0; i < 8; i++)
#pragma unroll
        for (int j = 0; j < 8; j++) acc[i][j] = 0ull;

    const float* ip = sIn + ly * ST;
    const float* wp = W + c0 * 64;

#pragma unroll 1
    for (int k = 0; k < 64; k += 4) {
        ulonglong2 w[8];
#pragma unroll
        for (int j = 0; j < 8; j++) w[j] = __ldg((const ulonglong2*)(wp + j * 64 + k));
#pragma unroll
        for (int i = 0; i < 8; i++) {
            ulonglong2 b = *(const ulonglong2*)(ip + i * (8 * ST) + k);
#pragma unroll
            for (int j = 0; j < 8; j++) {
                ffma2(acc[i][j], w[j].x, b.x);
                ffma2(acc[i][j], w[j].y, b.y);
            }
        }
    }

    float bb[8];
    if (bias) {
#pragma unroll
        for (int j = 0; j < 8; j++) bb[j] = __ldg(bias + c0 + j);
    } else {
#pragma unroll
        for (int j = 0; j < 8; j++) bb[j] = 0.f;
    }
#pragma unroll
    for (int i = 0; i < 8; i++) {
        float* op = sOut + (ly + 8 * i) * ST + c0;
#pragma unroll
        for (int q = 0; q < 2; q++) {
            float4 v;
            v.x = pairsum(acc[i][4*q+0]) + bb[4*q+0];
            v.y = pairsum(acc[i][4*q+1]) + bb[4*q+1];
            v.z = pairsum(acc[i][4*q+2]) + bb[4*q+2];
            v.w = pairsum(acc[i][4*q+3]) + bb[4*q+3];
            if (mode == 1) {
                v.x = gelu_exact(v.x); v.y = gelu_exact(v.y);
                v.z = gelu_exact(v.z); v.w = gelu_exact(v.w);
            } else if (mode == 2) {
                float4 d = *(const float4*)(op + 4*q);
                v.x += d.x; v.y += d.y; v.z += d.z; v.w += d.w;
            }
            *(float4*)(op + 4*q) = v;
        }
    }
}

// ---------------------------------------------------------------------------
// gemm16: 4-WARP single unit; warp w computes cols [16w, 16w+16).
// ---------------------------------------------------------------------------
__device__ __forceinline__ void gemm16(const float* sIn, const float* __restrict__ W,
                                       int wrs, int kof,
                                       const float* __restrict__ bias, float* sOut,
                                       int mode, int w, int lane)
{
    const int ly = lane & 7, lx = (lane >> 3) & 3;
    const int c0 = 16 * w + 4 * lx;
    unsigned long long acc[8][4];
#pragma unroll
    for (int i = 0; i < 8; i++)
#pragma unroll
        for (int j = 0; j < 4; j++) acc[i][j] = 0ull;

    const float* ip = sIn + ly * ST;
    const float* wp = W + c0 * wrs + kof;

#pragma unroll 1
    for (int k = 0; k < 64; k += 4) {
        ulonglong2 w4[4];
#pragma unroll
        for (int j = 0; j < 4; j++) w4[j] = __ldg((const ulonglong2*)(wp + j * wrs + k));
#pragma unroll
        for (int i = 0; i < 8; i++) {
            ulonglong2 b = *(const ulonglong2*)(ip + i * (8 * ST) + k);
#pragma unroll
            for (int j = 0; j < 4; j++) {
                ffma2(acc[i][j], w4[j].x, b.x);
                ffma2(acc[i][j], w4[j].y, b.y);
            }
        }
    }

    float4 bb;
    if (bias) bb = __ldg((const float4*)(bias + c0));
    else      bb = make_float4(0.f, 0.f, 0.f, 0.f);
#pragma unroll
    for (int i = 0; i < 8; i++) {
        float* op = sOut + (ly + 8 * i) * ST + c0;
        float4 v;
        v.x = pairsum(acc[i][0]) + bb.x; v.y = pairsum(acc[i][1]) + bb.y;
        v.z = pairsum(acc[i][2]) + bb.z; v.w = pairsum(acc[i][3]) + bb.w;
        if (mode == 1) {
            v.x = gelu_exact(v.x); v.y = gelu_exact(v.y);
            v.z = gelu_exact(v.z); v.w = gelu_exact(v.w);
        } else if (mode == 2) {
            float4 d = *(const float4*)op;
            v.x += d.x; v.y += d.y; v.z += d.z; v.w += d.w;
        }
        *(float4*)op = v;
    }
}

// Prologue: 4-warp, K=200, input rows from GLOBAL x (row stride 200).
__device__ __forceinline__ void gemm200(const float* __restrict__ gIn,
                                        const float* __restrict__ W,
                                        const float* __restrict__ bias, float* sOut,
                                        int w, int lane)
{
    const int ly = lane & 7, lx = (lane >> 3) & 3;
    const int c0 = 16 * w + 4 * lx;
    unsigned long long acc[8][4];
#pragma unroll
    for (int i = 0; i < 8; i++)
#pragma unroll
        for (int j = 0; j < 4; j++) acc[i][j] = 0ull;

    const float* ip = gIn + (size_t)ly * 200;
    const float* wp = W + c0 * 200;

#pragma unroll 1
    for (int k = 0; k < 200; k += 4) {
        ulonglong2 w4[4];
#pragma unroll
        for (int j = 0; j < 4; j++) w4[j] = __ldg((const ulonglong2*)(wp + j * 200 + k));
#pragma unroll
        for (int i = 0; i < 8; i++) {
            ulonglong2 b = __ldg((const ulonglong2*)(ip + (size_t)i * 8 * 200 + k));
#pragma unroll
            for (int j = 0; j < 4; j++) {
                ffma2(acc[i][j], w4[j].x, b.x);
                ffma2(acc[i][j], w4[j].y, b.y);
            }
        }
    }
    float4 bb = __ldg((const float4*)(bias + c0));
#pragma unroll
    for (int i = 0; i < 8; i++) {
        float* op = sOut + (ly + 8 * i) * ST + c0;
        float4 v;
        v.x = pairsum(acc[i][0]) + bb.x; v.y = pairsum(acc[i][1]) + bb.y;
        v.z = pairsum(acc[i][2]) + bb.z; v.w = pairsum(acc[i][3]) + bb.w;
        *(float4*)op = v;
    }
}

// LayerNorm, 2 threads per row: p = row base + 32*h; pair-reduce via shfl.bfly(1).
__device__ __forceinline__ void ln2(float* p, const float* __restrict__ g,
                                    const float* __restrict__ b, bool dogelu, int h)
{
    float4 v[8];
#pragma unroll
    for (int i = 0; i < 8; i++) v[i] = *(const float4*)(p + 4 * i);
    float s = 0.f;
#pragma unroll
    for (int i = 0; i < 8; i++) s += (v[i].x + v[i].y) + (v[i].z + v[i].w);
    s += __shfl_xor_sync(0xFFFFFFFFu, s, 1);
    float m = s * (1.0f / 64.0f);
    float qv = 0.f;
#pragma unroll
    for (int i = 0; i < 8; i++) {
        float dx = v[i].x - m, dy = v[i].y - m, dz = v[i].z - m, dw = v[i].w - m;
        qv = fmaf(dx, dx, qv); qv = fmaf(dy, dy, qv);
        qv = fmaf(dz, dz, qv); qv = fmaf(dw, dw, qv);
    }
    qv += __shfl_xor_sync(0xFFFFFFFFu, qv, 1);
    float inv = rsqrtf(qv * (1.0f / 64.0f) + 1e-5f);
#pragma unroll
    for (int i = 0; i < 8; i++) {
        float4 gg = __ldg((const float4*)(g + 32 * h + 4 * i));
        float4 bb = __ldg((const float4*)(b + 32 * h + 4 * i));
        float4 r;
        r.x = fmaf((v[i].x - m) * inv, gg.x, bb.x);
        r.y = fmaf((v[i].y - m) * inv, gg.y, bb.y);
        r.z = fmaf((v[i].z - m) * inv, gg.z, bb.z);
        r.w = fmaf((v[i].w - m) * inv, gg.w, bb.w);
        if (dogelu) {
            r.x = gelu_exact(r.x); r.y = gelu_exact(r.y);
            r.z = gelu_exact(r.z); r.w = gelu_exact(r.w);
        }
        *(float4*)(p + 4 * i) = r;
    }
}

// pair-phase macro: warps 0,1 -> unit A (col halves 0/1); warps 2,3 -> unit B.
#define PAIR(inA, WA, bA, oA, mA, inB, WB, bB, oB, mB) do {            \
    const float* gi; const float* gw; const float* gb; float* go; int gm; \
    if (wid < 2) { gi = (inA); gw = (WA); gb = (bA); go = (oA); gm = (mA); } \
    else         { gi = (inB); gw = (WB); gb = (bB); go = (oB); gm = (mB); } \
    gemm32(gi, gw, gb, go, gm, wid & 1, lane);                          \
    __syncthreads(); } while (0)

#define SINGLE(in, W, wrs, kof, b, o, m) do {                          \
    gemm16((in), (W), (wrs), (kof), (b), (o), (m), wid, lane);         \
    __syncthreads(); } while (0)

__global__ void __launch_bounds__(TPB, 2)
trm_kernel(const float* __restrict__ x,
           const float* __restrict__ W_in,     const float* __restrict__ b_in,
           const float* __restrict__ g_in,     const float* __restrict__ be_in,
           const float* __restrict__ z_in_w,   const float* __restrict__ z_in_b,
           const float* __restrict__ z_out_w,  const float* __restrict__ z_out_b,
           const float* __restrict__ z_ffn_w1, const float* __restrict__ z_ffn_b1,
           const float* __restrict__ z_ffn_w2, const float* __restrict__ z_ffn_b2,
           const float* __restrict__ zn1_g,    const float* __restrict__ zn1_b,
           const float* __restrict__ zn2_g,    const float* __restrict__ zn2_b,
           const float* __restrict__ y_in_w,   const float* __restrict__ y_in_b,
           const float* __restrict__ y_out_w,  const float* __restrict__ y_out_b,
           const float* __restrict__ y_ffn_w1, const float* __restrict__ y_ffn_b1,
           const float* __restrict__ y_ffn_w2, const float* __restrict__ y_ffn_b2,
           const float* __restrict__ yn1_g,    const float* __restrict__ yn1_b,
           const float* __restrict__ yn2_g,    const float* __restrict__ yn2_b,
           const float* __restrict__ W_out,    const float* __restrict__ b_out,
           float* __restrict__ out, int Btotal)
{
    extern __shared__ float sm[];
    float* sKX = sm + 0 * ROWS * ST;
    float* sVX = sm + 1 * ROWS * ST;
    float* sY  = sm + 2 * ROWS * ST;
    float* sZ  = sm + 3 * ROWS * ST;
    float* sSA = sm + 4 * ROWS * ST;
    float* sSB = sm + 5 * ROWS * ST;

    const int tid  = threadIdx.x;
    const int wid  = tid >> 5;
    const int lane = tid & 31;
    const int row0 = blockIdx.x * ROWS;
    // elementwise mapping: 2 threads per row; half eh owns cols [32eh, 32eh+32)
    // (= whole heads 2eh, 2eh+1 since D=16)
    const int erow = tid >> 1, eh = tid & 1;
    const int eoff = erow * ST + 32 * eh;

    const float* Wq = z_in_w;
    const float* Wk = z_in_w + 64 * 64;
    const float* Wv = z_in_w + 128 * 64;
    const float* bq = z_in_b;
    const float* bk = z_in_b + 64;
    const float* bv = z_in_b + 128;
    const float* Wvy = y_in_w + 128 * 64;
    const float* bvy = y_in_b + 128;

    // ---- prologue: x_proj = gelu(LN(x @ W_in^T + b_in)) -> SA ----
    gemm200(x + (size_t)row0 * 200, W_in, b_in, sSA, wid, lane);
    __syncthreads();
    ln2(sSA + eoff, g_in, be_in, true, eh);
    __syncthreads();
    // kx = xp@Wk^T+bk  ||  vx = xp@Wv^T+bv
    PAIR(sSA, Wk, bk, sKX, 0,  sSA, Wv, bv, sVX, 0);
    // zero y, z (all 128 threads)
    {
        float* yp = sY + eoff;
        float* zp = sZ + eoff;
        const float4 zz = make_float4(0.f, 0.f, 0.f, 0.f);
#pragma unroll
        for (int i = 0; i < 8; i++) { *(float4*)(yp + 4*i) = zz; *(float4*)(zp + 4*i) = zz; }
    }
    __syncthreads();

    // ---- 16 recursion steps ----
#pragma unroll 1
    for (int s = 0; s < NSTEPS; s++) {
        float qv[32];                       // q half, lives E1 -> E2 (across P2 only)
        float s0[2], s2[2], wa0[2], wa1[2], wa2[2];

        // P1: q(z) -> SA  ||  k(z) -> SB
        PAIR(sZ, Wq, bq, sSA, 0,  sZ, Wk, bk, sSB, 0);
        // E1: load q half to regs; s0 = q.kx, s2 = q.kz (2 heads, all local)
        {
            const float4* qp  = (const float4*)(sSA + eoff);
            const float4* kxp = (const float4*)(sKX + eoff);
            const float4* kzp = (const float4*)(sSB + eoff);
            s0[0] = s0[1] = s2[0] = s2[1] = 0.f;
#pragma unroll
            for (int i = 0; i < 8; i++) {
                float4 t = qp[i];
                qv[4*i] = t.x; qv[4*i+1] = t.y; qv[4*i+2] = t.z; qv[4*i+3] = t.w;
                int hh = i >> 2;
                float4 a = kxp[i];
                float4 c = kzp[i];
                s0[hh] = fmaf(t.x, a.x, fmaf(t.y, a.y, fmaf(t.z, a.z, fmaf(t.w, a.w, s0[hh]))));
                s2[hh] = fmaf(t.x, c.x, fmaf(t.y, c.y, fmaf(t.z, c.z, fmaf(t.w, c.w, s2[hh]))));
            }
        }
        __syncthreads();
        // P2: k(y) -> SB (q stays in registers)
        SINGLE(sY, Wk, 64, 0, bk, sSB, 0);
        // E2: s1 = q.ky ; softmax (fully local per thread, 2 heads)
        {
            const float4* kyp = (const float4*)(sSB + eoff);
            float s1[2] = {0.f, 0.f};
#pragma unroll
            for (int i = 0; i < 8; i++) {
                int hh = i >> 2;
                float4 a = kyp[i];
                s1[hh] = fmaf(qv[4*i], a.x, fmaf(qv[4*i+1], a.y,
                         fmaf(qv[4*i+2], a.z, fmaf(qv[4*i+3], a.w, s1[hh]))));
            }
#pragma unroll
            for (int hh = 0; hh < 2; hh++) {
                float a0 = s0[hh] * 0.25f, a1 = s1[hh] * 0.25f, a2 = s2[hh] * 0.25f;
                float mx = fmaxf(a0, fmaxf(a1, a2));
                float e0 = __expf(a0 - mx), e1 = __expf(a1 - mx), e2 = __expf(a2 - mx);
                float rs = 1.0f / (e0 + e1 + e2);
                wa0[hh] = e0 * rs; wa1[hh] = e1 * rs; wa2[hh] = e2 * rs;
            }
        }
        __syncthreads();
        // P3: v(y) -> SA  ||  v(z) -> SB
        PAIR(sY, Wv, bv, sSA, 0,  sZ, Wv, bv, sSB, 0);
        // E3: SA := wa0*vx + wa1*vy + wa2*vz
        {
            float* sap = sSA + eoff;
            const float4* sbp = (const float4*)(sSB + eoff);
            const float4* vxp = (const float4*)(sVX + eoff);
#pragma unroll
            for (int i = 0; i < 8; i++) {
                int hh = i >> 2;
                float4 a = vxp[i];
                float4 b2 = *(const float4*)(sap + 4*i);
                float4 c = sbp[i];
                float4 o;
                o.x = wa0[hh]*a.x + wa1[hh]*b2.x + wa2[hh]*c.x;
                o.y = wa0[hh]*a.y + wa1[hh]*b2.y + wa2[hh]*c.y;
                o.z = wa0[hh]*a.z + wa1[hh]*b2.z + wa2[hh]*c.z;
                o.w = wa0[hh]*a.w + wa1[hh]*b2.w + wa2[hh]*c.w;
                *(float4*)(sap + 4*i) = o;
            }
        }
        __syncthreads();
        // P4: z += SA @ z_out_w^T + z_out_b ; LN zn1
        SINGLE(sSA, z_out_w, 64, 0, z_out_b, sZ, 2);
        ln2(sZ + eoff, zn1_g, zn1_b, false, eh);
        __syncthreads();
        // P5: FFN z hidden: gelu -> SA (rows 0-63) || SB (rows 64-127)
        PAIR(sZ, z_ffn_w1, z_ffn_b1, sSA, 1,  sZ, z_ffn_w1 + 64*64, z_ffn_b1 + 64, sSB, 1);
        // P6: z += [SA|SB] @ w2^T + b2 ; LN zn2
        gemm16(sSA, z_ffn_w2, 128, 0,  z_ffn_b2, sZ, 2, wid, lane);
        gemm16(sSB, z_ffn_w2, 128, 64, (const float*)0, sZ, 2, wid, lane);
        __syncthreads();
        ln2(sZ + eoff, zn2_g, zn2_b, false, eh);
        __syncthreads();
        // P7: ca1: SA = z2 @ Wvy^T + bvy
        SINGLE(sZ, Wvy, 64, 0, bvy, sSA, 0);
        // P8: y += SA @ y_out_w^T + y_out_b ; LN yn1
        SINGLE(sSA, y_out_w, 64, 0, y_out_b, sY, 2);
        ln2(sY + eoff, yn1_g, yn1_b, false, eh);
        __syncthreads();
        // P9: FFN y hidden
        PAIR(sY, y_ffn_w1, y_ffn_b1, sSA, 1,  sY, y_ffn_w1 + 64*64, y_ffn_b1 + 64, sSB, 1);
        // P10: y += [SA|SB] @ w2^T + b2 ; LN yn2
        gemm16(sSA, y_ffn_w2, 128, 0,  y_ffn_b2, sY, 2, wid, lane);
        gemm16(sSB, y_ffn_w2, 128, 64, (const float*)0, sY, 2, wid, lane);
        __syncthreads();
        ln2(sY + eoff, yn2_g, yn2_b, false, eh);
        __syncthreads();
    }

    // ---- output: (y @ W_out^T + b_out)[:, 0]  (2 threads/row + pair reduce) ----
    {
        const float4* yp = (const float4*)(sY + eoff);
        float acc = 0.f;
#pragma unroll
        for (int i = 0; i < 8; i++) {
            float4 v = yp[i];
            float4 w = __ldg((const float4*)(W_out + 32 * eh + 4 * i));
            acc = fmaf(v.x, w.x, fmaf(v.y, w.y, fmaf(v.z, w.z, fmaf(v.w, w.w, acc))));
        }
        acc += __shfl_xor_sync(0xFFFFFFFFu, acc, 1);
        int r = row0 + erow;
        if (eh == 0 && r < Btotal) out[r] = acc + __ldg(b_out);
    }
}

extern "C" void kernel_launch(void* const* d_in, const int* in_sizes, int n_in,
                              void* d_out, int out_size)
{
    const float* x        = (const float*)d_in[0];
    const float* W_in     = (const float*)d_in[1];
    const float* b_in     = (const float*)d_in[2];
    const float* g_in     = (const float*)d_in[3];
    const float* be_in    = (const float*)d_in[4];
    const float* z_in_w   = (const float*)d_in[5];
    const float* z_in_b   = (const float*)d_in[6];
    const float* z_out_w  = (const float*)d_in[7];
    const float* z_out_b  = (const float*)d_in[8];
    const float* z_ffn_w1 = (const float*)d_in[9];
    const float* z_ffn_b1 = (const float*)d_in[10];
    const float* z_ffn_w2 = (const float*)d_in[11];
    const float* z_ffn_b2 = (const float*)d_in[12];
    const float* zn1_g    = (const float*)d_in[13];
    const float* zn1_b    = (const float*)d_in[14];
    const float* zn2_g    = (const float*)d_in[15];
    const float* zn2_b    = (const float*)d_in[16];
    const float* y_in_w   = (const float*)d_in[17];
    const float* y_in_b   = (const float*)d_in[18];
    const float* y_out_w  = (const float*)d_in[19];
    const float* y_out_b  = (const float*)d_in[20];
    const float* y_ffn_w1 = (const float*)d_in[21];
    const float* y_ffn_b1 = (const float*)d_in[22];
    const float* y_ffn_w2 = (const float*)d_in[23];
    const float* y_ffn_b2 = (const float*)d_in[24];
    const float* yn1_g    = (const float*)d_in[25];
    const float* yn1_b    = (const float*)d_in[26];
    const float* yn2_g    = (const float*)d_in[27];
    const float* yn2_b    = (const float*)d_in[28];
    const float* W_out    = (const float*)d_in[29];
    const float* b_out    = (const float*)d_in[30];
    float* out = (float*)d_out;

    int B = in_sizes[0] / 200;
    size_t smem = (size_t)6 * ROWS * ST * sizeof(float);   // 104448 B -> 2 CTAs/SM
    cudaFuncSetAttribute(trm_kernel, cudaFuncAttributeMaxDynamicSharedMemorySize, (int)smem);

    dim3 grid((B + ROWS - 1) / ROWS);
    trm_kernel<<<grid, TPB, smem>>>(x, W_in, b_in, g_in, be_in,
                                    z_in_w, z_in_b, z_out_w, z_out_b,
                                    z_ffn_w1, z_ffn_b1, z_ffn_w2, z_ffn_b2,
                                    zn1_g, zn1_b, zn2_g, zn2_b,
                                    y_in_w, y_in_b, y_out_w, y_out_b,
                                    y_ffn_w1, y_ffn_b1, y_ffn_w2, y_ffn_b2,
                                    yn1_g, yn1_b, yn2_g, yn2_b,
                                    W_out, b_out, out, B);
}

// round 11
// speedup vs baseline: 3.2246x; 1.0004x over previous
#include <cuda_runtime.h>

#define TPB    128
#define ROWS   64
#define ST     68          // buffer row stride in floats (68 % 32 == 4 -> conflict-free)
#define NSTEPS 16

__device__ __forceinline__ float gelu_exact(float v) {
    return 0.5f * v * (1.0f + erff(v * 0.70710678118654752f));
}

// packed fp32x2 FMA: acc.{lo,hi} += a.{lo,hi} * b.{lo,hi}   (FFMA2 on sm_103a)
__device__ __forceinline__ void ffma2(unsigned long long& acc,
                                      unsigned long long a, unsigned long long b) {
    asm("fma.rn.f32x2 %0, %1, %2, %0;" : "+l"(acc) : "l"(a), "l"(b));
}
// horizontal reduce of a packed pair
__device__ __forceinline__ float pairsum(unsigned long long v) {
    float lo, hi;
    asm("mov.b64 {%0, %1}, %2;" : "=f"(lo), "=f"(hi) : "l"(v));
    return lo + hi;
}

// ---------------------------------------------------------------------------
// gemm32: ONE WARP computes rows 0..63 x cols [32ch, 32ch+32); 8x8 per-lane
// tile, k-packed FFMA2 accumulators. mode: 0=store, 1=gelu+store, 2=add-dest.
// ---------------------------------------------------------------------------
__device__ __forceinline__ void gemm32(const float* sIn, const float* __restrict__ W,
                                       const float* __restrict__ bias, float* sOut,
                                       int mode, int ch, int lane)
{
    const int ly = lane & 7, lx = lane >> 3;
    const int c0 = 32 * ch + 8 * lx;
    unsigned long long acc[8][8];
#pragma unroll
    for (int i = 0; i < 8; i++)
#pragma unroll
        for (int j = 0; j < 8; j++) acc[i][j] = 0ull;

    const float* ip = sIn + ly * ST;
    const float* wp = W + c0 * 64;

#pragma unroll 1
    for (int k = 0; k < 64; k += 4) {
        ulonglong2 w[8];
#pragma unroll
        for (int j = 0; j < 8; j++) w[j] = __ldg((const ulonglong2*)(wp + j * 64 + k));
#pragma unroll
        for (int i = 0; i < 8; i++) {
            ulonglong2 b = *(const ulonglong2*)(ip + i * (8 * ST) + k);
#pragma unroll
            for (int j = 0; j < 8; j++) {
                ffma2(acc[i][j], w[j].x, b.x);
                ffma2(acc[i][j], w[j].y, b.y);
            }
        }
    }

    float bb[8];
    if (bias) {
#pragma unroll
        for (int j = 0; j < 8; j++) bb[j] = __ldg(bias + c0 + j);
    } else {
#pragma unroll
        for (int j = 0; j < 8; j++) bb[j] = 0.f;
    }
#pragma unroll
    for (int i = 0; i < 8; i++) {
        float* op = sOut + (ly + 8 * i) * ST + c0;
#pragma unroll
        for (int q = 0; q < 2; q++) {
            float4 v;
            v.x = pairsum(acc[i][4*q+0]) + bb[4*q+0];
            v.y = pairsum(acc[i][4*q+1]) + bb[4*q+1];
            v.z = pairsum(acc[i][4*q+2]) + bb[4*q+2];
            v.w = pairsum(acc[i][4*q+3]) + bb[4*q+3];
            if (mode == 1) {
                v.x = gelu_exact(v.x); v.y = gelu_exact(v.y);
                v.z = gelu_exact(v.z); v.w = gelu_exact(v.w);
            } else if (mode == 2) {
                float4 d = *(const float4*)(op + 4*q);
                v.x += d.x; v.y += d.y; v.z += d.z; v.w += d.w;
            }
            *(float4*)(op + 4*q) = v;
        }
    }
}

// ---------------------------------------------------------------------------
// gemm16: 4-WARP single unit; warp w computes cols [16w, 16w+16).
// ---------------------------------------------------------------------------
__device__ __forceinline__ void gemm16(const float* sIn, const float* __restrict__ W,
                                       int wrs, int kof,
                                       const float* __restrict__ bias, float* sOut,
                                       int mode, int w, int lane)
{
    const int ly = lane & 7, lx = (lane >> 3) & 3;
    const int c0 = 16 * w + 4 * lx;
    unsigned long long acc[8][4];
#pragma unroll
    for (int i = 0; i < 8; i++)
#pragma unroll
        for (int j = 0; j < 4; j++) acc[i][j] = 0ull;

    const float* ip = sIn + ly * ST;
    const float* wp = W + c0 * wrs + kof;

#pragma unroll 1
    for (int k = 0; k < 64; k += 4) {
        ulonglong2 w4[4];
#pragma unroll
        for (int j = 0; j < 4; j++) w4[j] = __ldg((const ulonglong2*)(wp + j * wrs + k));
#pragma unroll
        for (int i = 0; i < 8; i++) {
            ulonglong2 b = *(const ulonglong2*)(ip + i * (8 * ST) + k);
#pragma unroll
            for (int j = 0; j < 4; j++) {
                ffma2(acc[i][j], w4[j].x, b.x);
                ffma2(acc[i][j], w4[j].y, b.y);
            }
        }
    }

    float4 bb;
    if (bias) bb = __ldg((const float4*)(bias + c0));
    else      bb = make_float4(0.f, 0.f, 0.f, 0.f);
#pragma unroll
    for (int i = 0; i < 8; i++) {
        float* op = sOut + (ly + 8 * i) * ST + c0;
        float4 v;
        v.x = pairsum(acc[i][0]) + bb.x; v.y = pairsum(acc[i][1]) + bb.y;
        v.z = pairsum(acc[i][2]) + bb.z; v.w = pairsum(acc[i][3]) + bb.w;
        if (mode == 1) {
            v.x = gelu_exact(v.x); v.y = gelu_exact(v.y);
            v.z = gelu_exact(v.z); v.w = gelu_exact(v.w);
        } else if (mode == 2) {
            float4 d = *(const float4*)op;
            v.x += d.x; v.y += d.y; v.z += d.z; v.w += d.w;
        }
        *(float4*)op = v;
    }
}

// Prologue: 4-warp, K=200, input rows from GLOBAL x (row stride 200).
__device__ __forceinline__ void gemm200(const float* __restrict__ gIn,
                                        const float* __restrict__ W,
                                        const float* __restrict__ bias, float* sOut,
                                        int w, int lane)
{
    const int ly = lane & 7, lx = (lane >> 3) & 3;
    const int c0 = 16 * w + 4 * lx;
    unsigned long long acc[8][4];
#pragma unroll
    for (int i = 0; i < 8; i++)
#pragma unroll
        for (int j = 0; j < 4; j++) acc[i][j] = 0ull;

    const float* ip = gIn + (size_t)ly * 200;
    const float* wp = W + c0 * 200;

#pragma unroll 1
    for (int k = 0; k < 200; k += 4) {
        ulonglong2 w4[4];
#pragma unroll
        for (int j = 0; j < 4; j++) w4[j] = __ldg((const ulonglong2*)(wp + j * 200 + k));
#pragma unroll
        for (int i = 0; i < 8; i++) {
            ulonglong2 b = __ldg((const ulonglong2*)(ip + (size_t)i * 8 * 200 + k));
#pragma unroll
            for (int j = 0; j < 4; j++) {
                ffma2(acc[i][j], w4[j].x, b.x);
                ffma2(acc[i][j], w4[j].y, b.y);
            }
        }
    }
    float4 bb = __ldg((const float4*)(bias + c0));
#pragma unroll
    for (int i = 0; i < 8; i++) {
        float* op = sOut + (ly + 8 * i) * ST + c0;
        float4 v;
        v.x = pairsum(acc[i][0]) + bb.x; v.y = pairsum(acc[i][1]) + bb.y;
        v.z = pairsum(acc[i][2]) + bb.z; v.w = pairsum(acc[i][3]) + bb.w;
        *(float4*)op = v;
    }
}

// LayerNorm, 2 threads per row: p = row base + 32*h; pair-reduce via shfl.bfly(1).
__device__ __forceinline__ void ln2(float* p, const float* __restrict__ g,
                                    const float* __restrict__ b, bool dogelu, int h)
{
    float4 v[8];
#pragma unroll
    for (int i = 0; i < 8; i++) v[i] = *(const float4*)(p + 4 * i);
    float s = 0.f;
#pragma unroll
    for (int i = 0; i < 8; i++) s += (v[i].x + v[i].y) + (v[i].z + v[i].w);
    s += __shfl_xor_sync(0xFFFFFFFFu, s, 1);
    float m = s * (1.0f / 64.0f);
    float qv = 0.f;
#pragma unroll
    for (int i = 0; i < 8; i++) {
        float dx = v[i].x - m, dy = v[i].y - m, dz = v[i].z - m, dw = v[i].w - m;
        qv = fmaf(dx, dx, qv); qv = fmaf(dy, dy, qv);
        qv = fmaf(dz, dz, qv); qv = fmaf(dw, dw, qv);
    }
    qv += __shfl_xor_sync(0xFFFFFFFFu, qv, 1);
    float inv = rsqrtf(qv * (1.0f / 64.0f) + 1e-5f);
#pragma unroll
    for (int i = 0; i < 8; i++) {
        float4 gg = __ldg((const float4*)(g + 32 * h + 4 * i));
        float4 bb = __ldg((const float4*)(b + 32 * h + 4 * i));
        float4 r;
        r.x = fmaf((v[i].x - m) * inv, gg.x, bb.x);
        r.y = fmaf((v[i].y - m) * inv, gg.y, bb.y);
        r.z = fmaf((v[i].z - m) * inv, gg.z, bb.z);
        r.w = fmaf((v[i].w - m) * inv, gg.w, bb.w);
        if (dogelu) {
            r.x = gelu_exact(r.x); r.y = gelu_exact(r.y);
            r.z = gelu_exact(r.z); r.w = gelu_exact(r.w);
        }
        *(float4*)(p + 4 * i) = r;
    }
}

// pair-phase macro: warps 0,1 -> unit A (col halves 0/1); warps 2,3 -> unit B.
#define PAIR(inA, WA, bA, oA, mA, inB, WB, bB, oB, mB) do {            \
    const float* gi; const float* gw; const float* gb; float* go; int gm; \
    if (wid < 2) { gi = (inA); gw = (WA); gb = (bA); go = (oA); gm = (mA); } \
    else         { gi = (inB); gw = (WB); gb = (bB); go = (oB); gm = (mB); } \
    gemm32(gi, gw, gb, go, gm, wid & 1, lane);                          \
    __syncthreads(); } while (0)

#define SINGLE(in, W, wrs, kof, b, o, m) do {                          \
    gemm16((in), (W), (wrs), (kof), (b), (o), (m), wid, lane);         \
    __syncthreads(); } while (0)

__global__ void __launch_bounds__(TPB, 2)
trm_kernel(const float* __restrict__ x,
           const float* __restrict__ W_in,     const float* __restrict__ b_in,
           const float* __restrict__ g_in,     const float* __restrict__ be_in,
           const float* __restrict__ z_in_w,   const float* __restrict__ z_in_b,
           const float* __restrict__ z_out_w,  const float* __restrict__ z_out_b,
           const float* __restrict__ z_ffn_w1, const float* __restrict__ z_ffn_b1,
           const float* __restrict__ z_ffn_w2, const float* __restrict__ z_ffn_b2,
           const float* __restrict__ zn1_g,    const float* __restrict__ zn1_b,
           const float* __restrict__ zn2_g,    const float* __restrict__ zn2_b,
           const float* __restrict__ y_in_w,   const float* __restrict__ y_in_b,
           const float* __restrict__ y_out_w,  const float* __restrict__ y_out_b,
           const float* __restrict__ y_ffn_w1, const float* __restrict__ y_ffn_b1,
           const float* __restrict__ y_ffn_w2, const float* __restrict__ y_ffn_b2,
           const float* __restrict__ yn1_g,    const float* __restrict__ yn1_b,
           const float* __restrict__ yn2_g,    const float* __restrict__ yn2_b,
           const float* __restrict__ W_out,    const float* __restrict__ b_out,
           float* __restrict__ out, int Btotal)
{
    extern __shared__ float sm[];
    float* sKX = sm + 0 * ROWS * ST;
    float* sVX = sm + 1 * ROWS * ST;
    float* sY  = sm + 2 * ROWS * ST;
    float* sZ  = sm + 3 * ROWS * ST;
    float* sSA = sm + 4 * ROWS * ST;
    float* sSB = sm + 5 * ROWS * ST;

    const int tid  = threadIdx.x;
    const int wid  = tid >> 5;
    const int lane = tid & 31;
    const int row0 = blockIdx.x * ROWS;
    // elementwise mapping: 2 threads per row; half eh owns cols [32eh, 32eh+32)
    // (= whole heads 2eh, 2eh+1 since D=16)
    const int erow = tid >> 1, eh = tid & 1;
    const int eoff = erow * ST + 32 * eh;

    const float* Wq = z_in_w;
    const float* Wk = z_in_w + 64 * 64;
    const float* Wv = z_in_w + 128 * 64;
    const float* bq = z_in_b;
    const float* bk = z_in_b + 64;
    const float* bv = z_in_b + 128;
    const float* Wvy = y_in_w + 128 * 64;
    const float* bvy = y_in_b + 128;

    // ---- prologue: x_proj = gelu(LN(x @ W_in^T + b_in)) -> SA ----
    gemm200(x + (size_t)row0 * 200, W_in, b_in, sSA, wid, lane);
    __syncthreads();
    ln2(sSA + eoff, g_in, be_in, true, eh);
    __syncthreads();
    // kx = xp@Wk^T+bk  ||  vx = xp@Wv^T+bv
    PAIR(sSA, Wk, bk, sKX, 0,  sSA, Wv, bv, sVX, 0);
    // zero y, z (all 128 threads)
    {
        float* yp = sY + eoff;
        float* zp = sZ + eoff;
        const float4 zz = make_float4(0.f, 0.f, 0.f, 0.f);
#pragma unroll
        for (int i = 0; i < 8; i++) { *(float4*)(yp + 4*i) = zz; *(float4*)(zp + 4*i) = zz; }
    }
    __syncthreads();

    // ---- 16 recursion steps ----
#pragma unroll 1
    for (int s = 0; s < NSTEPS; s++) {
        float qv[32];                       // q half, lives E1 -> E2 (across P2 only)
        float s0[2], s2[2], wa0[2], wa1[2], wa2[2];

        // P1: q(z) -> SA  ||  k(z) -> SB
        PAIR(sZ, Wq, bq, sSA, 0,  sZ, Wk, bk, sSB, 0);
        // E1: load q half to regs; s0 = q.kx, s2 = q.kz (2 heads, all local)
        {
            const float4* qp  = (const float4*)(sSA + eoff);
            const float4* kxp = (const float4*)(sKX + eoff);
            const float4* kzp = (const float4*)(sSB + eoff);
            s0[0] = s0[1] = s2[0] = s2[1] = 0.f;
#pragma unroll
            for (int i = 0; i < 8; i++) {
                float4 t = qp[i];
                qv[4*i] = t.x; qv[4*i+1] = t.y; qv[4*i+2] = t.z; qv[4*i+3] = t.w;
                int hh = i >> 2;
                float4 a = kxp[i];
                float4 c = kzp[i];
                s0[hh] = fmaf(t.x, a.x, fmaf(t.y, a.y, fmaf(t.z, a.z, fmaf(t.w, a.w, s0[hh]))));
                s2[hh] = fmaf(t.x, c.x, fmaf(t.y, c.y, fmaf(t.z, c.z, fmaf(t.w, c.w, s2[hh]))));
            }
        }
        __syncthreads();
        // P2: k(y) -> SB (q stays in registers)
        SINGLE(sY, Wk, 64, 0, bk, sSB, 0);
        // E2: s1 = q.ky ; softmax (fully local per thread, 2 heads)
        {
            const float4* kyp = (const float4*)(sSB + eoff);
            float s1[2] = {0.f, 0.f};
#pragma unroll
            for (int i = 0; i < 8; i++) {
                int hh = i >> 2;
                float4 a = kyp[i];
                s1[hh] = fmaf(qv[4*i], a.x, fmaf(qv[4*i+1], a.y,
                         fmaf(qv[4*i+2], a.z, fmaf(qv[4*i+3], a.w, s1[hh]))));
            }
#pragma unroll
            for (int hh = 0; hh < 2; hh++) {
                float a0 = s0[hh] * 0.25f, a1 = s1[hh] * 0.25f, a2 = s2[hh] * 0.25f;
                float mx = fmaxf(a0, fmaxf(a1, a2));
                float e0 = __expf(a0 - mx), e1 = __expf(a1 - mx), e2 = __expf(a2 - mx);
                float rs = 1.0f / (e0 + e1 + e2);
                wa0[hh] = e0 * rs; wa1[hh] = e1 * rs; wa2[hh] = e2 * rs;
            }
        }
        __syncthreads();
        // P3: v(y) -> SA  ||  v(z) -> SB
        PAIR(sY, Wv, bv, sSA, 0,  sZ, Wv, bv, sSB, 0);
        // E3: SA := wa0*vx + wa1*vy + wa2*vz
        {
            float* sap = sSA + eoff;
            const float4* sbp = (const float4*)(sSB + eoff);
            const float4* vxp = (const float4*)(sVX + eoff);
#pragma unroll
            for (int i = 0; i < 8; i++) {
                int hh = i >> 2;
                float4 a = vxp[i];
                float4 b2 = *(const float4*)(sap + 4*i);
                float4 c = sbp[i];
                float4 o;
                o.x = wa0[hh]*a.x + wa1[hh]*b2.x + wa2[hh]*c.x;
                o.y = wa0[hh]*a.y + wa1[hh]*b2.y + wa2[hh]*c.y;
                o.z = wa0[hh]*a.z + wa1[hh]*b2.z + wa2[hh]*c.z;
                o.w = wa0[hh]*a.w + wa1[hh]*b2.w + wa2[hh]*c.w;
                *(float4*)(sap + 4*i) = o;
            }
        }
        __syncthreads();
        // P4: z += SA @ z_out_w^T + z_out_b ; LN zn1
        SINGLE(sSA, z_out_w, 64, 0, z_out_b, sZ, 2);
        ln2(sZ + eoff, zn1_g, zn1_b, false, eh);
        __syncthreads();
        // P5: FFN z hidden: gelu -> SA (rows 0-63) || SB (rows 64-127)
        PAIR(sZ, z_ffn_w1, z_ffn_b1, sSA, 1,  sZ, z_ffn_w1 + 64*64, z_ffn_b1 + 64, sSB, 1);
        // P6: z += [SA|SB] @ w2^T + b2 ; LN zn2
        gemm16(sSA, z_ffn_w2, 128, 0,  z_ffn_b2, sZ, 2, wid, lane);
        gemm16(sSB, z_ffn_w2, 128, 64, (const float*)0, sZ, 2, wid, lane);
        __syncthreads();
        ln2(sZ + eoff, zn2_g, zn2_b, false, eh);
        __syncthreads();
        // P7: ca1: SA = z2 @ Wvy^T + bvy
        SINGLE(sZ, Wvy, 64, 0, bvy, sSA, 0);
        // P8: y += SA @ y_out_w^T + y_out_b ; LN yn1
        SINGLE(sSA, y_out_w, 64, 0, y_out_b, sY, 2);
        ln2(sY + eoff, yn1_g, yn1_b, false, eh);
        __syncthreads();
        // P9: FFN y hidden
        PAIR(sY, y_ffn_w1, y_ffn_b1, sSA, 1,  sY, y_ffn_w1 + 64*64, y_ffn_b1 + 64, sSB, 1);
        // P10: y += [SA|SB] @ w2^T + b2 ; LN yn2
        gemm16(sSA, y_ffn_w2, 128, 0,  y_ffn_b2, sY, 2, wid, lane);
        gemm16(sSB, y_ffn_w2, 128, 64, (const float*)0, sY, 2, wid, lane);
        __syncthreads();
        ln2(sY + eoff, yn2_g, yn2_b, false, eh);
        __syncthreads();
    }

    // ---- output: (y @ W_out^T + b_out)[:, 0]  (2 threads/row + pair reduce) ----
    {
        const float4* yp = (const float4*)(sY + eoff);
        float acc = 0.f;
#pragma unroll
        for (int i = 0; i < 8; i++) {
            float4 v = yp[i];
            float4 w = __ldg((const float4*)(W_out + 32 * eh + 4 * i));
            acc = fmaf(v.x, w.x, fmaf(v.y, w.y, fmaf(v.z, w.z, fmaf(v.w, w.w, acc))));
        }
        acc += __shfl_xor_sync(0xFFFFFFFFu, acc, 1);
        int r = row0 + erow;
        if (eh == 0 && r < Btotal) out[r] = acc + __ldg(b_out);
    }
}

extern "C" void kernel_launch(void* const* d_in, const int* in_sizes, int n_in,
                              void* d_out, int out_size)
{
    const float* x        = (const float*)d_in[0];
    const float* W_in     = (const float*)d_in[1];
    const float* b_in     = (const float*)d_in[2];
    const float* g_in     = (const float*)d_in[3];
    const float* be_in    = (const float*)d_in[4];
    const float* z_in_w   = (const float*)d_in[5];
    const float* z_in_b   = (const float*)d_in[6];
    const float* z_out_w  = (const float*)d_in[7];
    const float* z_out_b  = (const float*)d_in[8];
    const float* z_ffn_w1 = (const float*)d_in[9];
    const float* z_ffn_b1 = (const float*)d_in[10];
    const float* z_ffn_w2 = (const float*)d_in[11];
    const float* z_ffn_b2 = (const float*)d_in[12];
    const float* zn1_g    = (const float*)d_in[13];
    const float* zn1_b    = (const float*)d_in[14];
    const float* zn2_g    = (const float*)d_in[15];
    const float* zn2_b    = (const float*)d_in[16];
    const float* y_in_w   = (const float*)d_in[17];
    const float* y_in_b   = (const float*)d_in[18];
    const float* y_out_w  = (const float*)d_in[19];
    const float* y_out_b  = (const float*)d_in[20];
    const float* y_ffn_w1 = (const float*)d_in[21];
    const float* y_ffn_b1 = (const float*)d_in[22];
    const float* y_ffn_w2 = (const float*)d_in[23];
    const float* y_ffn_b2 = (const float*)d_in[24];
    const float* yn1_g    = (const float*)d_in[25];
    const float* yn1_b    = (const float*)d_in[26];
    const float* yn2_g    = (const float*)d_in[27];
    const float* yn2_b    = (const float*)d_in[28];
    const float* W_out    = (const float*)d_in[29];
    const float* b_out    = (const float*)d_in[30];
    float* out = (float*)d_out;

    int B = in_sizes[0] / 200;
    size_t smem = (size_t)6 * ROWS * ST * sizeof(float);   // 104448 B -> 2 CTAs/SM
    cudaFuncSetAttribute(trm_kernel, cudaFuncAttributeMaxDynamicSharedMemorySize, (int)smem);

    dim3 grid((B + ROWS - 1) / ROWS);
    trm_kernel<<<grid, TPB, smem>>>(x, W_in, b_in, g_in, be_in,
                                    z_in_w, z_in_b, z_out_w, z_out_b,
                                    z_ffn_w1, z_ffn_b1, z_ffn_w2, z_ffn_b2,
                                    zn1_g, zn1_b, zn2_g, zn2_b,
                                    y_in_w, y_in_b, y_out_w, y_out_b,
                                    y_ffn_w1, y_ffn_b1, y_ffn_w2, y_ffn_b2,
                                    yn1_g, yn1_b, yn2_g, yn2_b,
                                    W_out, b_out, out, B);
}